// round 1
// baseline (speedup 1.0000x reference)
#include <cuda_runtime.h>
#include <math.h>

// Problem constants
#define NRAYS   8192
#define TSAMP   128
#define HID     128
#define SHDIM   16
#define RAYEXT  10.0f

// ---------------- f32x2 packed-FMA helpers (sm_100+) ----------------
__device__ __forceinline__ unsigned long long pk2(float v) {
    unsigned long long r;
    asm("mov.b64 %0, {%1, %2};" : "=l"(r) : "f"(v), "f"(v));
    return r;
}
__device__ __forceinline__ void upk2(unsigned long long v, float& lo, float& hi) {
    asm("mov.b64 {%0, %1}, %2;" : "=f"(lo), "=f"(hi) : "l"(v));
}
__device__ __forceinline__ void ffma2(unsigned long long& d,
                                      unsigned long long a,
                                      unsigned long long b) {
    asm("fma.rn.f32x2 %0, %1, %2, %0;" : "+l"(d) : "l"(a), "l"(b));
}

// ---------------- shared-memory layout (floats) ----------------
#define OFF_W2   0          // [128][128]  (k-major, same as input)
#define OFF_H1T  16384      // [k][t]      (hidden-major, sample-minor)
#define OFF_H2   32768      // [t][132]    (sample-major, padded)
#define H2_STR   132
#define OFF_W1   49664      // 3*128
#define OFF_B1   50048      // 128
#define OFF_B2   50176      // 128
#define OFF_WD   50304      // 128
#define OFF_WC   50432      // 144*3
#define OFF_BC   50864      // bc[3] + bd at [3]
#define OFF_TS   50868      // 128
#define OFF_X    50996      // 128
#define OFF_Y    51124      // 128
#define OFF_Z    51252      // 128
#define OFF_MASK 51380      // 128
#define OFF_WSUM 51508      // 8
#define OFF_RED  51516      // 32
#define SMEM_FLOATS 51548
#define SMEM_BYTES  (SMEM_FLOATS * 4)

__device__ __forceinline__ void sh3(float x, float y, float z, float* Y) {
    float x2 = x*x, y2 = y*y, z2 = z*z;
    float xy = x*y, yz = y*z, xz = x*z;
    Y[0]  = 0.282094791773878f;
    Y[1]  = -0.48860251190292f * y;
    Y[2]  = 0.48860251190292f * z;
    Y[3]  = -0.48860251190292f * x;
    Y[4]  = 1.0925484305920792f * xy;
    Y[5]  = -1.0925484305920792f * yz;
    Y[6]  = 0.94617469575756f * z2 - 0.31539156525252f;
    Y[7]  = -1.0925484305920792f * xz;
    Y[8]  = 0.5462742152960396f * (x2 - y2);
    Y[9]  = 0.5900435899266435f * y * (-3.0f * x2 + y2);
    Y[10] = 2.8906114426405538f * xy * z;
    Y[11] = 0.4570457994644658f * y * (1.0f - 5.0f * z2);
    Y[12] = 0.3731763325901154f * z * (5.0f * z2 - 3.0f);
    Y[13] = 0.4570457994644658f * x * (1.0f - 5.0f * z2);
    Y[14] = 1.445305721320277f * z * (x2 - y2);
    Y[15] = 0.5900435899266435f * x * (-x2 + 3.0f * y2);
}

__global__ __launch_bounds__(256, 1)
void radiance_kernel(const float* __restrict__ origins,
                     const float* __restrict__ dirs,
                     const float* __restrict__ u,
                     const float* __restrict__ W1,
                     const float* __restrict__ b1,
                     const float* __restrict__ W2,
                     const float* __restrict__ b2,
                     const float* __restrict__ Wd,
                     const float* __restrict__ bd,
                     const float* __restrict__ Wc,
                     const float* __restrict__ bc,
                     float* __restrict__ out)
{
    extern __shared__ float sm[];
    float* sW2  = sm + OFF_W2;
    float* sH1T = sm + OFF_H1T;
    float* sH2  = sm + OFF_H2;
    float* sW1  = sm + OFF_W1;
    float* sb1  = sm + OFF_B1;
    float* sb2  = sm + OFF_B2;
    float* sWd  = sm + OFF_WD;
    float* sWc  = sm + OFF_WC;
    float* sbc  = sm + OFF_BC;
    float* sTs  = sm + OFF_TS;
    float* sX   = sm + OFF_X;
    float* sY   = sm + OFF_Y;
    float* sZ   = sm + OFF_Z;
    float* sMask= sm + OFF_MASK;
    float* sWsum= sm + OFF_WSUM;
    float* sRed = sm + OFF_RED;

    const int tid = threadIdx.x;
    const int r   = blockIdx.x;

    // ---------- phase 0: stage weights to SMEM ----------
    {
        const float4* g4 = (const float4*)W2;
        float4* s4 = (float4*)sW2;
        #pragma unroll 4
        for (int i = tid; i < 4096; i += 256) s4[i] = g4[i];
        for (int i = tid; i < 384; i += 256) sW1[i] = W1[i];
        if (tid < 128) {
            sb1[tid] = b1[tid];
            sb2[tid] = b2[tid];
            sWd[tid] = Wd[tid];
        }
        for (int i = tid; i < 432; i += 256) sWc[i] = Wc[i];
        if (tid < 3) sbc[tid] = bc[tid];
        if (tid == 3) sbc[3] = bd[0];
    }

    // ---------- phase A: ray setup (all threads, redundant) ----------
    const float ox = __ldg(origins + 3*r + 0);
    const float oy = __ldg(origins + 3*r + 1);
    const float oz = __ldg(origins + 3*r + 2);
    const float dx = __ldg(dirs + 3*r + 0);
    const float dy = __ldg(dirs + 3*r + 1);
    const float dz = __ldg(dirs + 3*r + 2);

    float i0 = 1.0f/dx, i1 = 1.0f/dy, i2 = 1.0f/dz;
    float a0 = (-1.0f - ox)*i0, b0 = (1.0f - ox)*i0;
    float a1 = (-1.0f - oy)*i1, b1_ = (1.0f - oy)*i1;
    float a2 = (-1.0f - oz)*i2, b2_ = (1.0f - oz)*i2;
    float mn0 = fminf(a0,b0), mx0 = fmaxf(a0,b0);
    float mn1 = fminf(a1,b1_), mx1 = fmaxf(a1,b1_);
    float mn2 = fminf(a2,b2_), mx2 = fmaxf(a2,b2_);
    float tnear = fmaxf(fmaxf(fmaxf(mn0, mn1), mn2), 0.0f);
    float tfar  = fminf(fminf(mx0, mx1), mx2);
    bool  active = (tfar > tnear);
    float tfar_c = fmaxf(tfar, tnear + 1e-3f);
    float dnorm = sqrtf(dx*dx + dy*dy + dz*dz);

    // ---------- phase B: sample positions (threads < 128) ----------
    if (tid < TSAMP) {
        float uu = __ldg(u + r*TSAMP + tid);
        float frac = ((float)tid + uu) * (1.0f/(float)TSAMP);
        float ts = tnear + (tfar_c - tnear) * frac;
        float px = ox + dx*ts, py = oy + dy*ts, pz = oz + dz*ts;
        bool inb = (fabsf(px) <= 1.0f) && (fabsf(py) <= 1.0f) && (fabsf(pz) <= 1.0f);
        sTs[tid] = ts;
        sX[tid] = px; sY[tid] = py; sZ[tid] = pz;
        sMask[tid] = (inb && active) ? 1.0f : 0.0f;
    }
    __syncthreads();

    // ---------- phase C: H1 = relu(X @ W1 + b1), stored [j][t] ----------
    {
        int t  = tid & 127;
        int j0 = (tid >> 7) * 64;
        float px = sX[t], py = sY[t], pz = sZ[t];
        #pragma unroll 8
        for (int j = j0; j < j0 + 64; j++) {
            float v = fmaf(px, sW1[j],
                      fmaf(py, sW1[128 + j],
                      fmaf(pz, sW1[256 + j], sb1[j])));
            sH1T[j*128 + t] = fmaxf(v, 0.0f);
        }
    }
    __syncthreads();

    // ---------- phase D: H2 = relu(H1 @ W2 + b2), 128x128x128 GEMM ----------
    {
        const int ti = tid >> 4;   // 0..15 : sample tile
        const int tj = tid & 15;   // 0..15 : hidden tile
        unsigned long long acc[8][4];
        #pragma unroll
        for (int i = 0; i < 8; i++)
            #pragma unroll
            for (int p = 0; p < 4; p++) acc[i][p] = 0ull;

        const float* aBase = sH1T + ti*8;
        const ulonglong2* wBase = ((const ulonglong2*)sW2) + tj*2;

        #pragma unroll 2
        for (int k = 0; k < 128; k++) {
            const float* ap = aBase + k*128;
            float4 aA = *(const float4*)(ap);
            float4 aB = *(const float4*)(ap + 4);
            unsigned long long av[8];
            av[0] = pk2(aA.x); av[1] = pk2(aA.y); av[2] = pk2(aA.z); av[3] = pk2(aA.w);
            av[4] = pk2(aB.x); av[5] = pk2(aB.y); av[6] = pk2(aB.z); av[7] = pk2(aB.w);
            ulonglong2 wlo = wBase[k*32];
            ulonglong2 whi = wBase[k*32 + 1];
            #pragma unroll
            for (int i = 0; i < 8; i++) {
                ffma2(acc[i][0], av[i], wlo.x);
                ffma2(acc[i][1], av[i], wlo.y);
                ffma2(acc[i][2], av[i], whi.x);
                ffma2(acc[i][3], av[i], whi.y);
            }
        }

        // bias + relu + store to sH2 [t][132]
        const int c = tj*8;
        float bb[8];
        #pragma unroll
        for (int p = 0; p < 8; p++) bb[p] = sb2[c + p];
        #pragma unroll
        for (int i = 0; i < 8; i++) {
            int row = ti*8 + i;
            float4 lo, hi;
            upk2(acc[i][0], lo.x, lo.y);
            upk2(acc[i][1], lo.z, lo.w);
            upk2(acc[i][2], hi.x, hi.y);
            upk2(acc[i][3], hi.z, hi.w);
            lo.x = fmaxf(lo.x + bb[0], 0.0f);
            lo.y = fmaxf(lo.y + bb[1], 0.0f);
            lo.z = fmaxf(lo.z + bb[2], 0.0f);
            lo.w = fmaxf(lo.w + bb[3], 0.0f);
            hi.x = fmaxf(hi.x + bb[4], 0.0f);
            hi.y = fmaxf(hi.y + bb[5], 0.0f);
            hi.z = fmaxf(hi.z + bb[6], 0.0f);
            hi.w = fmaxf(hi.w + bb[7], 0.0f);
            *(float4*)(sH2 + row*H2_STR + c)     = lo;
            *(float4*)(sH2 + row*H2_STR + c + 4) = hi;
        }
    }
    __syncthreads();

    // ---------- phase E: heads + per-sample quantities ----------
    float my_sd = 0.0f, mc0 = 0.0f, mc1 = 0.0f, mc2 = 0.0f;
    if (tid < TSAMP) {
        const float* hrow = sH2 + tid*H2_STR;
        float accd = 0.0f, ac0 = 0.0f, ac1 = 0.0f, ac2 = 0.0f;
        #pragma unroll 8
        for (int k = 0; k < HID; k += 4) {
            float4 h = *(const float4*)(hrow + k);
            accd += h.x*sWd[k] + h.y*sWd[k+1] + h.z*sWd[k+2] + h.w*sWd[k+3];
            ac0  += h.x*sWc[3*k+0] + h.y*sWc[3*k+3] + h.z*sWc[3*k+6] + h.w*sWc[3*k+9];
            ac1  += h.x*sWc[3*k+1] + h.y*sWc[3*k+4] + h.z*sWc[3*k+7] + h.w*sWc[3*k+10];
            ac2  += h.x*sWc[3*k+2] + h.y*sWc[3*k+5] + h.z*sWc[3*k+8] + h.w*sWc[3*k+11];
        }
        // SH conditioning part of Wc (rows 128..143)
        float inv_n = 1.0f / dnorm;
        float Ysh[16];
        sh3(dx*inv_n, dy*inv_n, dz*inv_n, Ysh);
        #pragma unroll
        for (int q = 0; q < SHDIM; q++) {
            float wq = Ysh[q];
            ac0 += wq * sWc[(HID + q)*3 + 0];
            ac1 += wq * sWc[(HID + q)*3 + 1];
            ac2 += wq * sWc[(HID + q)*3 + 2];
        }
        // sigma = softplus(.) ; color = sigmoid(.)
        float zz = accd + sbc[3];
        float sig = fmaxf(zz, 0.0f) + log1pf(expf(-fabsf(zz)));
        float m = sMask[tid];
        sig *= m;
        mc0 = m / (1.0f + expf(-(ac0 + sbc[0])));
        mc1 = m / (1.0f + expf(-(ac1 + sbc[1])));
        mc2 = m / (1.0f + expf(-(ac2 + sbc[2])));
        float tsv  = sTs[tid];
        float tnxt = (tid < TSAMP - 1) ? sTs[tid + 1] : (tfar_c * RAYEXT);
        my_sd = sig * (tnxt - tsv) * dnorm;
    }

    // ---------- inclusive scan of sd over 128 samples ----------
    const int lane = tid & 31;
    const int wrp  = tid >> 5;
    float v = my_sd;
    #pragma unroll
    for (int o = 1; o < 32; o <<= 1) {
        float n = __shfl_up_sync(0xffffffffu, v, o);
        if (lane >= o) v += n;
    }
    if (lane == 31) sWsum[wrp] = v;
    __syncthreads();
    float woff = 0.0f;
    #pragma unroll
    for (int q = 0; q < 4; q++) woff += (q < wrp) ? sWsum[q] : 0.0f;
    float csum = v + woff;

    float wgt = 0.0f;
    if (tid < TSAMP) wgt = expf(my_sd - csum) - expf(-csum);
    float rc0 = wgt * mc0, rc1 = wgt * mc1, rc2 = wgt * mc2;

    // ---------- block reduction ----------
    #pragma unroll
    for (int o = 16; o; o >>= 1) {
        rc0 += __shfl_xor_sync(0xffffffffu, rc0, o);
        rc1 += __shfl_xor_sync(0xffffffffu, rc1, o);
        rc2 += __shfl_xor_sync(0xffffffffu, rc2, o);
        wgt += __shfl_xor_sync(0xffffffffu, wgt, o);
    }
    if (lane == 0) {
        sRed[wrp*4 + 0] = rc0;
        sRed[wrp*4 + 1] = rc1;
        sRed[wrp*4 + 2] = rc2;
        sRed[wrp*4 + 3] = wgt;
    }
    __syncthreads();
    if (tid == 0) {
        float o0 = 0.0f, o1 = 0.0f, o2 = 0.0f, o3 = 0.0f;
        #pragma unroll
        for (int q = 0; q < 8; q++) {
            o0 += sRed[q*4 + 0];
            o1 += sRed[q*4 + 1];
            o2 += sRed[q*4 + 2];
            o3 += sRed[q*4 + 3];
        }
        float4 res;
        res.x = active ? o0 : 0.0f;
        res.y = active ? o1 : 0.0f;
        res.z = active ? o2 : 0.0f;
        res.w = active ? o3 : 0.0f;
        *(float4*)(out + (size_t)r*4) = res;
    }
}

extern "C" void kernel_launch(void* const* d_in, const int* in_sizes, int n_in,
                              void* d_out, int out_size) {
    const float* origins = (const float*)d_in[0];
    const float* dirs    = (const float*)d_in[1];
    const float* u       = (const float*)d_in[2];
    const float* W1      = (const float*)d_in[3];
    const float* b1      = (const float*)d_in[4];
    const float* W2      = (const float*)d_in[5];
    const float* b2      = (const float*)d_in[6];
    const float* Wd      = (const float*)d_in[7];
    const float* bd      = (const float*)d_in[8];
    const float* Wc      = (const float*)d_in[9];
    const float* bc      = (const float*)d_in[10];
    float* out = (float*)d_out;

    cudaFuncSetAttribute(radiance_kernel,
                         cudaFuncAttributeMaxDynamicSharedMemorySize, SMEM_BYTES);
    radiance_kernel<<<NRAYS, 256, SMEM_BYTES>>>(
        origins, dirs, u, W1, b1, W2, b2, Wd, bd, Wc, bc, out);
}

// round 3
// speedup vs baseline: 2.3298x; 2.3298x over previous
#include <cuda_runtime.h>
#include <cuda_bf16.h>
#include <cstdint>
#include <math.h>

// Problem constants
#define NRAYS   8192
#define TSAMP   128
#define HID     128
#define SHDIM   16
#define RAYEXT  10.0f

// ---------------- warp-level tensor-core helpers (sm_80+ ISA, valid on sm_103) ----
__device__ __forceinline__ void ldsm_x4(uint32_t* r, uint32_t addr) {
    asm volatile("ldmatrix.sync.aligned.m8n8.x4.shared.b16 {%0,%1,%2,%3}, [%4];"
        : "=r"(r[0]), "=r"(r[1]), "=r"(r[2]), "=r"(r[3]) : "r"(addr));
}
__device__ __forceinline__ void ldsm_x4_t(uint32_t* r, uint32_t addr) {
    asm volatile("ldmatrix.sync.aligned.m8n8.x4.trans.shared.b16 {%0,%1,%2,%3}, [%4];"
        : "=r"(r[0]), "=r"(r[1]), "=r"(r[2]), "=r"(r[3]) : "r"(addr));
}
__device__ __forceinline__ void mma_bf16(float* d, const uint32_t* a,
                                         uint32_t b0, uint32_t b1) {
    asm volatile("mma.sync.aligned.m16n8k16.row.col.f32.bf16.bf16.f32 "
        "{%0,%1,%2,%3}, {%4,%5,%6,%7}, {%8,%9}, {%0,%1,%2,%3};"
        : "+f"(d[0]), "+f"(d[1]), "+f"(d[2]), "+f"(d[3])
        : "r"(a[0]), "r"(a[1]), "r"(a[2]), "r"(a[3]), "r"(b0), "r"(b1));
}
__device__ __forceinline__ uint32_t smem_u32(const void* p) {
    uint32_t a;
    asm("{ .reg .u64 t; cvta.to.shared.u64 t, %1; cvt.u32.u64 %0, t; }"
        : "=r"(a) : "l"(p));
    return a;
}
__device__ __forceinline__ uint32_t pack_bf2(__nv_bfloat16 a, __nv_bfloat16 b) {
    __nv_bfloat162 t = __halves2bfloat162(a, b);
    return *reinterpret_cast<uint32_t*>(&t);
}

// ---------------- SMEM layout ----------------
// bf16 tiles, row stride 136 elements = 272 bytes (16B-aligned, conflict-free LDSM)
#define TSTRIDE  272
#define OFF_AHI  0
#define OFF_ALO  34816
#define OFF_BHI  69632
#define OFF_BLO  104448
#define OFF_F    139264
// float-region offsets (in floats)
#define F_W1   0       // 384
#define F_B1   384     // 128
#define F_B2   512     // 128
#define F_WD   640     // 128
#define F_WC   768     // 432
#define F_BC   1200    // 4 (bc0,bc1,bc2,bd)
#define F_TS   1216    // 128
#define F_X    1344
#define F_Y    1472
#define F_Z    1600
#define F_MSK  1728
#define F_WS   1856    // 8
#define F_RED  1864    // 32
#define F_HEAD 1896    // 128*4
#define F_TOTAL 2408
#define SMEM_BYTES (OFF_F + F_TOTAL * 4)

__device__ __forceinline__ void sh3(float x, float y, float z, float* Y) {
    float x2 = x*x, y2 = y*y, z2 = z*z;
    float xy = x*y, yz = y*z, xz = x*z;
    Y[0]  = 0.282094791773878f;
    Y[1]  = -0.48860251190292f * y;
    Y[2]  = 0.48860251190292f * z;
    Y[3]  = -0.48860251190292f * x;
    Y[4]  = 1.0925484305920792f * xy;
    Y[5]  = -1.0925484305920792f * yz;
    Y[6]  = 0.94617469575756f * z2 - 0.31539156525252f;
    Y[7]  = -1.0925484305920792f * xz;
    Y[8]  = 0.5462742152960396f * (x2 - y2);
    Y[9]  = 0.5900435899266435f * y * (-3.0f * x2 + y2);
    Y[10] = 2.8906114426405538f * xy * z;
    Y[11] = 0.4570457994644658f * y * (1.0f - 5.0f * z2);
    Y[12] = 0.3731763325901154f * z * (5.0f * z2 - 3.0f);
    Y[13] = 0.4570457994644658f * x * (1.0f - 5.0f * z2);
    Y[14] = 1.445305721320277f * z * (x2 - y2);
    Y[15] = 0.5900435899266435f * x * (-x2 + 3.0f * y2);
}

__device__ __forceinline__ void split_bf16(float v, __nv_bfloat16& hi, __nv_bfloat16& lo) {
    hi = __float2bfloat16(v);
    lo = __float2bfloat16(v - __bfloat162float(hi));
}

__global__ __launch_bounds__(256, 1)
void radiance_kernel(const float* __restrict__ origins,
                     const float* __restrict__ dirs,
                     const float* __restrict__ u,
                     const float* __restrict__ W1,
                     const float* __restrict__ b1,
                     const float* __restrict__ W2,
                     const float* __restrict__ b2,
                     const float* __restrict__ Wd,
                     const float* __restrict__ bd,
                     const float* __restrict__ Wc,
                     const float* __restrict__ bc,
                     float* __restrict__ out)
{
    extern __shared__ char smc[];
    float* sf   = (float*)(smc + OFF_F);
    float* sW1  = sf + F_W1;
    float* sB1  = sf + F_B1;
    float* sB2  = sf + F_B2;
    float* sWD  = sf + F_WD;
    float* sWC  = sf + F_WC;
    float* sBC  = sf + F_BC;
    float* sTS  = sf + F_TS;
    float* sX   = sf + F_X;
    float* sY   = sf + F_Y;
    float* sZ   = sf + F_Z;
    float* sMSK = sf + F_MSK;
    float* sWS  = sf + F_WS;
    float* sRED = sf + F_RED;
    float* sHEAD= sf + F_HEAD;

    const uint32_t sbase = smem_u32(smc);
    const int tid  = threadIdx.x;
    const int wid  = tid >> 5;
    const int lane = tid & 31;
    const int r    = blockIdx.x;

    // ---------- stage small weights ----------
    for (int i = tid; i < 384; i += 256) sW1[i] = W1[i];
    if (tid < 128) {
        sB1[tid] = b1[tid];
        sB2[tid] = b2[tid];
        sWD[tid] = Wd[tid];
    }
    for (int i = tid; i < 432; i += 256) sWC[i] = Wc[i];
    if (tid < 3) sBC[tid] = bc[tid];
    if (tid == 3) sBC[3] = bd[0];

    // ---------- stage W2 -> Bhi/Blo [k][n] bf16 (native layout, coalesced) ----------
    {
        #pragma unroll
        for (int g = 0; g < 16; g++) {
            int idx4 = g * 256 + tid;          // 0..4095 (float4 index)
            int k    = idx4 >> 5;              // 0..127
            int n4   = (idx4 & 31) << 2;       // 0..124
            float4 v = __ldg((const float4*)W2 + idx4);
            __nv_bfloat16 h0, h1, h2, h3, l0, l1, l2, l3;
            split_bf16(v.x, h0, l0);
            split_bf16(v.y, h1, l1);
            split_bf16(v.z, h2, l2);
            split_bf16(v.w, h3, l3);
            uint32_t off = (uint32_t)(k * TSTRIDE + n4 * 2);
            *(uint2*)(smc + OFF_BHI + off) = make_uint2(pack_bf2(h0, h1), pack_bf2(h2, h3));
            *(uint2*)(smc + OFF_BLO + off) = make_uint2(pack_bf2(l0, l1), pack_bf2(l2, l3));
        }
    }

    // ---------- ray setup (all threads, redundant) ----------
    const float ox = __ldg(origins + 3*r + 0);
    const float oy = __ldg(origins + 3*r + 1);
    const float oz = __ldg(origins + 3*r + 2);
    const float dx = __ldg(dirs + 3*r + 0);
    const float dy = __ldg(dirs + 3*r + 1);
    const float dz = __ldg(dirs + 3*r + 2);

    float i0 = 1.0f/dx, i1 = 1.0f/dy, i2 = 1.0f/dz;
    float a0 = (-1.0f - ox)*i0, b0 = (1.0f - ox)*i0;
    float a1 = (-1.0f - oy)*i1, b1_ = (1.0f - oy)*i1;
    float a2 = (-1.0f - oz)*i2, b2_ = (1.0f - oz)*i2;
    float mn0 = fminf(a0,b0), mx0 = fmaxf(a0,b0);
    float mn1 = fminf(a1,b1_), mx1 = fmaxf(a1,b1_);
    float mn2 = fminf(a2,b2_), mx2 = fmaxf(a2,b2_);
    float tnear = fmaxf(fmaxf(fmaxf(mn0, mn1), mn2), 0.0f);
    float tfar  = fminf(fminf(mx0, mx1), mx2);
    bool  active = (tfar > tnear);
    float tfar_c = fmaxf(tfar, tnear + 1e-3f);
    float dnorm = sqrtf(dx*dx + dy*dy + dz*dz);

    // ---------- sample positions (threads < 128) ----------
    if (tid < TSAMP) {
        float uu = __ldg(u + r*TSAMP + tid);
        float frac = ((float)tid + uu) * (1.0f/(float)TSAMP);
        float ts = tnear + (tfar_c - tnear) * frac;
        float px = ox + dx*ts, py = oy + dy*ts, pz = oz + dz*ts;
        bool inb = (fabsf(px) <= 1.0f) && (fabsf(py) <= 1.0f) && (fabsf(pz) <= 1.0f);
        sTS[tid] = ts;
        sX[tid] = px; sY[tid] = py; sZ[tid] = pz;
        sMSK[tid] = (inb && active) ? 1.0f : 0.0f;
    }
    __syncthreads();

    // ---------- layer1: A = relu(X@W1+b1) -> bf16 hi/lo tiles [t][k] ----------
    {
        int t  = tid & 127;
        int j0 = (tid >> 7) * 64;
        float px = sX[t], py = sY[t], pz = sZ[t];
        #pragma unroll
        for (int g = 0; g < 8; g++) {
            uint32_t hp[4], lp[4];
            #pragma unroll
            for (int i = 0; i < 8; i += 2) {
                int j = j0 + g*8 + i;
                float v0 = fmaf(px, sW1[j],
                           fmaf(py, sW1[128 + j],
                           fmaf(pz, sW1[256 + j], sB1[j])));
                float v1 = fmaf(px, sW1[j + 1],
                           fmaf(py, sW1[128 + j + 1],
                           fmaf(pz, sW1[256 + j + 1], sB1[j + 1])));
                v0 = fmaxf(v0, 0.0f);
                v1 = fmaxf(v1, 0.0f);
                __nv_bfloat16 h0, h1, l0, l1;
                split_bf16(v0, h0, l0);
                split_bf16(v1, h1, l1);
                hp[i >> 1] = pack_bf2(h0, h1);
                lp[i >> 1] = pack_bf2(l0, l1);
            }
            uint32_t off = (uint32_t)(t * TSTRIDE + (j0 + g*8) * 2);
            *(uint4*)(smc + OFF_AHI + off) = make_uint4(hp[0], hp[1], hp[2], hp[3]);
            *(uint4*)(smc + OFF_ALO + off) = make_uint4(lp[0], lp[1], lp[2], lp[3]);
        }
    }
    __syncthreads();

    // ---------- tensor GEMM: D = Ahi*Bhi + Ahi*Blo + Alo*Bhi (m16n8k16 bf16) ----------
    // Warp w owns output rows [16w, 16w+16), all 128 cols (16 j-tiles of 8).
    float acc[16][4];
    #pragma unroll
    for (int j = 0; j < 16; j++)
        #pragma unroll
        for (int p = 0; p < 4; p++) acc[j][p] = 0.0f;

    {
        const uint32_t aHiBase = sbase + OFF_AHI
            + (uint32_t)((wid*16 + (lane & 15)) * TSTRIDE + (lane >> 4) * 16);
        const uint32_t aLoBase = aHiBase + (OFF_ALO - OFF_AHI);
        const int gg = lane >> 3, ii = lane & 7;
        const uint32_t bRow = (uint32_t)(((gg & 1)*8 + ii) * TSTRIDE + (gg >> 1) * 16);
        const uint32_t bHiBase = sbase + OFF_BHI + bRow;
        const uint32_t bLoBase = bHiBase + (OFF_BLO - OFF_BHI);

        #pragma unroll
        for (int s = 0; s < 8; s++) {
            uint32_t ah[4], al[4];
            ldsm_x4(ah, aHiBase + s*32);
            ldsm_x4(al, aLoBase + s*32);
            #pragma unroll
            for (int jp = 0; jp < 8; jp++) {
                uint32_t bh[4], bl[4];
                ldsm_x4_t(bh, bHiBase + s*(16*TSTRIDE) + jp*32);
                ldsm_x4_t(bl, bLoBase + s*(16*TSTRIDE) + jp*32);
                mma_bf16(acc[2*jp],     ah, bh[0], bh[1]);
                mma_bf16(acc[2*jp],     ah, bl[0], bl[1]);
                mma_bf16(acc[2*jp],     al, bh[0], bh[1]);
                mma_bf16(acc[2*jp + 1], ah, bh[2], bh[3]);
                mma_bf16(acc[2*jp + 1], ah, bl[2], bl[3]);
                mma_bf16(acc[2*jp + 1], al, bh[2], bh[3]);
            }
        }
    }

    // ---------- heads directly from fragments ----------
    // Thread holds rows (16w + lane/4) and (+8), cols j*8 + (lane%4)*2 + {0,1}.
    {
        float hd0 = 0.0f, hd1 = 0.0f;
        float c00 = 0.0f, c01 = 0.0f, c02 = 0.0f;
        float c10 = 0.0f, c11 = 0.0f, c12 = 0.0f;
        const int cb = (lane & 3) * 2;
        #pragma unroll
        for (int j = 0; j < 16; j++) {
            int c = j*8 + cb;
            float2 b2v = *(const float2*)(sB2 + c);
            float2 wdv = *(const float2*)(sWD + c);
            float h00 = fmaxf(acc[j][0] + b2v.x, 0.0f);
            float h01 = fmaxf(acc[j][1] + b2v.y, 0.0f);
            float h80 = fmaxf(acc[j][2] + b2v.x, 0.0f);
            float h81 = fmaxf(acc[j][3] + b2v.y, 0.0f);
            hd0 = fmaf(h00, wdv.x, fmaf(h01, wdv.y, hd0));
            hd1 = fmaf(h80, wdv.x, fmaf(h81, wdv.y, hd1));
            float w0x = sWC[3*c+0], w0y = sWC[3*c+1], w0z = sWC[3*c+2];
            float w1x = sWC[3*c+3], w1y = sWC[3*c+4], w1z = sWC[3*c+5];
            c00 = fmaf(h00, w0x, fmaf(h01, w1x, c00));
            c01 = fmaf(h00, w0y, fmaf(h01, w1y, c01));
            c02 = fmaf(h00, w0z, fmaf(h01, w1z, c02));
            c10 = fmaf(h80, w0x, fmaf(h81, w1x, c10));
            c11 = fmaf(h80, w0y, fmaf(h81, w1y, c11));
            c12 = fmaf(h80, w0z, fmaf(h81, w1z, c12));
        }
        // quad reduce (cols split across lane%4)
        #pragma unroll
        for (int o = 1; o <= 2; o <<= 1) {
            hd0 += __shfl_xor_sync(0xffffffffu, hd0, o);
            hd1 += __shfl_xor_sync(0xffffffffu, hd1, o);
            c00 += __shfl_xor_sync(0xffffffffu, c00, o);
            c01 += __shfl_xor_sync(0xffffffffu, c01, o);
            c02 += __shfl_xor_sync(0xffffffffu, c02, o);
            c10 += __shfl_xor_sync(0xffffffffu, c10, o);
            c11 += __shfl_xor_sync(0xffffffffu, c11, o);
            c12 += __shfl_xor_sync(0xffffffffu, c12, o);
        }
        if ((lane & 3) == 0) {
            int t0 = wid*16 + (lane >> 2);
            sHEAD[t0*4 + 0] = hd0;
            sHEAD[t0*4 + 1] = c00;
            sHEAD[t0*4 + 2] = c01;
            sHEAD[t0*4 + 3] = c02;
            sHEAD[(t0+8)*4 + 0] = hd1;
            sHEAD[(t0+8)*4 + 1] = c10;
            sHEAD[(t0+8)*4 + 2] = c11;
            sHEAD[(t0+8)*4 + 3] = c12;
        }
    }
    __syncthreads();

    // ---------- per-sample activations + sd (threads < 128) ----------
    float my_sd = 0.0f, mc0 = 0.0f, mc1 = 0.0f, mc2 = 0.0f;
    if (tid < TSAMP) {
        float accd = sHEAD[tid*4 + 0];
        float ac0  = sHEAD[tid*4 + 1];
        float ac1  = sHEAD[tid*4 + 2];
        float ac2  = sHEAD[tid*4 + 3];
        // SH conditioning (rows 128..143 of Wc)
        float inv_n = 1.0f / dnorm;
        float Ysh[16];
        sh3(dx*inv_n, dy*inv_n, dz*inv_n, Ysh);
        #pragma unroll
        for (int q = 0; q < SHDIM; q++) {
            float wq = Ysh[q];
            ac0 = fmaf(wq, sWC[(HID + q)*3 + 0], ac0);
            ac1 = fmaf(wq, sWC[(HID + q)*3 + 1], ac1);
            ac2 = fmaf(wq, sWC[(HID + q)*3 + 2], ac2);
        }
        float zz = accd + sBC[3];
        float sig = fmaxf(zz, 0.0f) + log1pf(expf(-fabsf(zz)));
        float m = sMSK[tid];
        sig *= m;
        mc0 = m / (1.0f + expf(-(ac0 + sBC[0])));
        mc1 = m / (1.0f + expf(-(ac1 + sBC[1])));
        mc2 = m / (1.0f + expf(-(ac2 + sBC[2])));
        float tsv  = sTS[tid];
        float tnxt = (tid < TSAMP - 1) ? sTS[tid + 1] : (tfar_c * RAYEXT);
        my_sd = sig * (tnxt - tsv) * dnorm;
    }

    // ---------- inclusive scan of sd over samples ----------
    float v = my_sd;
    #pragma unroll
    for (int o = 1; o < 32; o <<= 1) {
        float n = __shfl_up_sync(0xffffffffu, v, o);
        if (lane >= o) v += n;
    }
    if (lane == 31) sWS[wid] = v;
    __syncthreads();
    float woff = 0.0f;
    #pragma unroll
    for (int q = 0; q < 4; q++) woff += (q < wid) ? sWS[q] : 0.0f;
    float csum = v + woff;

    float wgt = 0.0f;
    if (tid < TSAMP) wgt = expf(my_sd - csum) - expf(-csum);
    float rc0 = wgt * mc0, rc1 = wgt * mc1, rc2 = wgt * mc2;

    // ---------- block reduction ----------
    #pragma unroll
    for (int o = 16; o; o >>= 1) {
        rc0 += __shfl_xor_sync(0xffffffffu, rc0, o);
        rc1 += __shfl_xor_sync(0xffffffffu, rc1, o);
        rc2 += __shfl_xor_sync(0xffffffffu, rc2, o);
        wgt += __shfl_xor_sync(0xffffffffu, wgt, o);
    }
    if (lane == 0) {
        sRED[wid*4 + 0] = rc0;
        sRED[wid*4 + 1] = rc1;
        sRED[wid*4 + 2] = rc2;
        sRED[wid*4 + 3] = wgt;
    }
    __syncthreads();
    if (tid == 0) {
        float o0 = 0.0f, o1 = 0.0f, o2 = 0.0f, o3 = 0.0f;
        #pragma unroll
        for (int q = 0; q < 8; q++) {
            o0 += sRED[q*4 + 0];
            o1 += sRED[q*4 + 1];
            o2 += sRED[q*4 + 2];
            o3 += sRED[q*4 + 3];
        }
        float4 res;
        res.x = active ? o0 : 0.0f;
        res.y = active ? o1 : 0.0f;
        res.z = active ? o2 : 0.0f;
        res.w = active ? o3 : 0.0f;
        *(float4*)(out + (size_t)r*4) = res;
    }
}

extern "C" void kernel_launch(void* const* d_in, const int* in_sizes, int n_in,
                              void* d_out, int out_size) {
    const float* origins = (const float*)d_in[0];
    const float* dirs    = (const float*)d_in[1];
    const float* u       = (const float*)d_in[2];
    const float* W1      = (const float*)d_in[3];
    const float* b1      = (const float*)d_in[4];
    const float* W2      = (const float*)d_in[5];
    const float* b2      = (const float*)d_in[6];
    const float* Wd      = (const float*)d_in[7];
    const float* bd      = (const float*)d_in[8];
    const float* Wc      = (const float*)d_in[9];
    const float* bc      = (const float*)d_in[10];
    float* out = (float*)d_out;

    cudaFuncSetAttribute(radiance_kernel,
                         cudaFuncAttributeMaxDynamicSharedMemorySize, SMEM_BYTES);
    radiance_kernel<<<NRAYS, 256, SMEM_BYTES>>>(
        origins, dirs, u, W1, b1, W2, b2, Wd, bd, Wc, bc, out);
}

// round 4
// speedup vs baseline: 2.8015x; 1.2025x over previous
#include <cuda_runtime.h>
#include <cuda_bf16.h>
#include <cstdint>
#include <math.h>

// Problem constants
#define NRAYS   8192
#define TSAMP   128
#define HID     128
#define SHDIM   16
#define RAYEXT  10.0f
#define NTHREADS 512

// ---------------- warp-level tensor-core helpers ----------------
__device__ __forceinline__ void ldsm_x4(uint32_t* r, uint32_t addr) {
    asm volatile("ldmatrix.sync.aligned.m8n8.x4.shared.b16 {%0,%1,%2,%3}, [%4];"
        : "=r"(r[0]), "=r"(r[1]), "=r"(r[2]), "=r"(r[3]) : "r"(addr));
}
__device__ __forceinline__ void ldsm_x4_t(uint32_t* r, uint32_t addr) {
    asm volatile("ldmatrix.sync.aligned.m8n8.x4.trans.shared.b16 {%0,%1,%2,%3}, [%4];"
        : "=r"(r[0]), "=r"(r[1]), "=r"(r[2]), "=r"(r[3]) : "r"(addr));
}
__device__ __forceinline__ void mma_bf16(float* d, const uint32_t* a,
                                         uint32_t b0, uint32_t b1) {
    asm volatile("mma.sync.aligned.m16n8k16.row.col.f32.bf16.bf16.f32 "
        "{%0,%1,%2,%3}, {%4,%5,%6,%7}, {%8,%9}, {%0,%1,%2,%3};"
        : "+f"(d[0]), "+f"(d[1]), "+f"(d[2]), "+f"(d[3])
        : "r"(a[0]), "r"(a[1]), "r"(a[2]), "r"(a[3]), "r"(b0), "r"(b1));
}
__device__ __forceinline__ uint32_t smem_u32(const void* p) {
    uint32_t a;
    asm("{ .reg .u64 t; cvta.to.shared.u64 t, %1; cvt.u32.u64 %0, t; }"
        : "=r"(a) : "l"(p));
    return a;
}
__device__ __forceinline__ uint32_t pack_bf2(__nv_bfloat16 a, __nv_bfloat16 b) {
    __nv_bfloat162 t = __halves2bfloat162(a, b);
    return *reinterpret_cast<uint32_t*>(&t);
}

// ---------------- SMEM layout ----------------
// bf16 tiles, row stride 136 elements = 272 bytes (16B-aligned, conflict-free LDSM)
#define TSTRIDE  272
#define TILE_SZ  34816          // 128 * 272
#define OFF_AHI  0
#define OFF_ALO  34816
#define OFF_BHI  69632
#define OFF_BLO  104448
#define OFF_F    139264
// float-region offsets (in floats)
#define F_W1   0       // 384
#define F_B1   384     // 128
#define F_B2   512     // 128
#define F_WD   640     // 128
#define F_WC   768     // 432
#define F_BC   1200    // 4 (bc0,bc1,bc2,bd)
#define F_TS   1216    // 128
#define F_X    1344
#define F_Y    1472
#define F_Z    1600
#define F_MSK  1728
#define F_WS   1856    // 8
#define F_RED  1864    // 64
#define F_HA   1928    // 128*4  (heads, even-col-half warps)
#define F_HB   2440    // 128*4  (heads, odd-col-half warps)
#define F_TOTAL 2952
#define SMEM_BYTES (OFF_F + F_TOTAL * 4)

__device__ __forceinline__ void sh3(float x, float y, float z, float* Y) {
    float x2 = x*x, y2 = y*y, z2 = z*z;
    float xy = x*y, yz = y*z, xz = x*z;
    Y[0]  = 0.282094791773878f;
    Y[1]  = -0.48860251190292f * y;
    Y[2]  = 0.48860251190292f * z;
    Y[3]  = -0.48860251190292f * x;
    Y[4]  = 1.0925484305920792f * xy;
    Y[5]  = -1.0925484305920792f * yz;
    Y[6]  = 0.94617469575756f * z2 - 0.31539156525252f;
    Y[7]  = -1.0925484305920792f * xz;
    Y[8]  = 0.5462742152960396f * (x2 - y2);
    Y[9]  = 0.5900435899266435f * y * (-3.0f * x2 + y2);
    Y[10] = 2.8906114426405538f * xy * z;
    Y[11] = 0.4570457994644658f * y * (1.0f - 5.0f * z2);
    Y[12] = 0.3731763325901154f * z * (5.0f * z2 - 3.0f);
    Y[13] = 0.4570457994644658f * x * (1.0f - 5.0f * z2);
    Y[14] = 1.445305721320277f * z * (x2 - y2);
    Y[15] = 0.5900435899266435f * x * (-x2 + 3.0f * y2);
}

__device__ __forceinline__ void split_bf16(float v, __nv_bfloat16& hi, __nv_bfloat16& lo) {
    hi = __float2bfloat16(v);
    lo = __float2bfloat16(v - __bfloat162float(hi));
}

__global__ __launch_bounds__(NTHREADS, 1)
void radiance_kernel(const float* __restrict__ origins,
                     const float* __restrict__ dirs,
                     const float* __restrict__ u,
                     const float* __restrict__ W1,
                     const float* __restrict__ b1,
                     const float* __restrict__ W2,
                     const float* __restrict__ b2,
                     const float* __restrict__ Wd,
                     const float* __restrict__ bd,
                     const float* __restrict__ Wc,
                     const float* __restrict__ bc,
                     float* __restrict__ out)
{
    extern __shared__ char smc[];
    float* sf   = (float*)(smc + OFF_F);
    float* sW1  = sf + F_W1;
    float* sB1  = sf + F_B1;
    float* sB2  = sf + F_B2;
    float* sWD  = sf + F_WD;
    float* sWC  = sf + F_WC;
    float* sBC  = sf + F_BC;
    float* sTS  = sf + F_TS;
    float* sX   = sf + F_X;
    float* sY   = sf + F_Y;
    float* sZ   = sf + F_Z;
    float* sMSK = sf + F_MSK;
    float* sWS  = sf + F_WS;
    float* sRED = sf + F_RED;
    float* sHA  = sf + F_HA;
    float* sHB  = sf + F_HB;

    const uint32_t sbase = smem_u32(smc);
    const int tid  = threadIdx.x;
    const int wid  = tid >> 5;
    const int lane = tid & 31;

    // ================= one-time staging (persistent CTA) =================
    for (int i = tid; i < 384; i += NTHREADS) sW1[i] = W1[i];
    if (tid < 128) {
        sB1[tid] = b1[tid];
        sB2[tid] = b2[tid];
        sWD[tid] = Wd[tid];
    }
    for (int i = tid; i < 432; i += NTHREADS) sWC[i] = Wc[i];
    if (tid < 3) sBC[tid] = bc[tid];
    if (tid == 3) sBC[3] = bd[0];

    // W2 -> Bhi/Blo [k][n] bf16 (native layout, coalesced)
    {
        #pragma unroll
        for (int g = 0; g < 8; g++) {
            int idx4 = g * NTHREADS + tid;     // 0..4095 (float4 index)
            int k    = idx4 >> 5;              // 0..127
            int n4   = (idx4 & 31) << 2;       // 0..124
            float4 v = __ldg((const float4*)W2 + idx4);
            __nv_bfloat16 h0, h1, h2, h3, l0, l1, l2, l3;
            split_bf16(v.x, h0, l0);
            split_bf16(v.y, h1, l1);
            split_bf16(v.z, h2, l2);
            split_bf16(v.w, h3, l3);
            uint32_t off = (uint32_t)(k * TSTRIDE + n4 * 2);
            *(uint2*)(smc + OFF_BHI + off) = make_uint2(pack_bf2(h0, h1), pack_bf2(h2, h3));
            *(uint2*)(smc + OFF_BLO + off) = make_uint2(pack_bf2(l0, l1), pack_bf2(l2, l3));
        }
    }
    __syncthreads();

    // GEMM addressing (fixed per thread):
    // Warp w: rows [16*(w>>1), +16), cols [64*(w&1), +64)
    const uint32_t aHiBase = sbase + OFF_AHI
        + (uint32_t)(((wid >> 1)*16 + (lane & 15)) * TSTRIDE + (lane >> 4) * 16);
    const uint32_t aLoBase = aHiBase + TILE_SZ;
    const int gg = lane >> 3, ii = lane & 7;
    const uint32_t bRow = (uint32_t)(((gg & 1)*8 + ii) * TSTRIDE + (gg >> 1) * 16);
    const uint32_t bHiBase = sbase + OFF_BHI + bRow + (uint32_t)((wid & 1) * 128);
    const uint32_t bLoBase = bHiBase + TILE_SZ;

    // ================= persistent ray loop =================
    for (int r = blockIdx.x; r < NRAYS; r += gridDim.x) {

        // ---------- ray setup (redundant across threads, cheap) ----------
        const float ox = __ldg(origins + 3*r + 0);
        const float oy = __ldg(origins + 3*r + 1);
        const float oz = __ldg(origins + 3*r + 2);
        const float dx = __ldg(dirs + 3*r + 0);
        const float dy = __ldg(dirs + 3*r + 1);
        const float dz = __ldg(dirs + 3*r + 2);

        float i0 = 1.0f/dx, i1 = 1.0f/dy, i2 = 1.0f/dz;
        float a0 = (-1.0f - ox)*i0, b0 = (1.0f - ox)*i0;
        float a1 = (-1.0f - oy)*i1, b1_ = (1.0f - oy)*i1;
        float a2 = (-1.0f - oz)*i2, b2_ = (1.0f - oz)*i2;
        float mn0 = fminf(a0,b0), mx0 = fmaxf(a0,b0);
        float mn1 = fminf(a1,b1_), mx1 = fmaxf(a1,b1_);
        float mn2 = fminf(a2,b2_), mx2 = fmaxf(a2,b2_);
        float tnear = fmaxf(fmaxf(fmaxf(mn0, mn1), mn2), 0.0f);
        float tfar  = fminf(fminf(mx0, mx1), mx2);
        bool  active = (tfar > tnear);
        float tfar_c = fmaxf(tfar, tnear + 1e-3f);
        float dnorm = sqrtf(dx*dx + dy*dy + dz*dz);

        // ---------- sample positions (threads < 128) ----------
        if (tid < TSAMP) {
            float uu = __ldg(u + r*TSAMP + tid);
            float frac = ((float)tid + uu) * (1.0f/(float)TSAMP);
            float ts = tnear + (tfar_c - tnear) * frac;
            float px = ox + dx*ts, py = oy + dy*ts, pz = oz + dz*ts;
            bool inb = (fabsf(px) <= 1.0f) && (fabsf(py) <= 1.0f) && (fabsf(pz) <= 1.0f);
            sTS[tid] = ts;
            sX[tid] = px; sY[tid] = py; sZ[tid] = pz;
            sMSK[tid] = (inb && active) ? 1.0f : 0.0f;
        }
        __syncthreads();

        // ---------- layer1: A = relu(X@W1+b1) -> bf16 hi/lo tiles [t][k] ----------
        {
            int t  = tid & 127;
            int j0 = (tid >> 7) * 32;
            float px = sX[t], py = sY[t], pz = sZ[t];
            #pragma unroll
            for (int g = 0; g < 4; g++) {
                uint32_t hp[4], lp[4];
                #pragma unroll
                for (int i = 0; i < 8; i += 2) {
                    int j = j0 + g*8 + i;
                    float v0 = fmaf(px, sW1[j],
                               fmaf(py, sW1[128 + j],
                               fmaf(pz, sW1[256 + j], sB1[j])));
                    float v1 = fmaf(px, sW1[j + 1],
                               fmaf(py, sW1[128 + j + 1],
                               fmaf(pz, sW1[256 + j + 1], sB1[j + 1])));
                    v0 = fmaxf(v0, 0.0f);
                    v1 = fmaxf(v1, 0.0f);
                    __nv_bfloat16 h0, h1, l0, l1;
                    split_bf16(v0, h0, l0);
                    split_bf16(v1, h1, l1);
                    hp[i >> 1] = pack_bf2(h0, h1);
                    lp[i >> 1] = pack_bf2(l0, l1);
                }
                uint32_t off = (uint32_t)(t * TSTRIDE + (j0 + g*8) * 2);
                *(uint4*)(smc + OFF_AHI + off) = make_uint4(hp[0], hp[1], hp[2], hp[3]);
                *(uint4*)(smc + OFF_ALO + off) = make_uint4(lp[0], lp[1], lp[2], lp[3]);
            }
        }
        __syncthreads();

        // ---------- tensor GEMM: D = Ahi*Bhi + Ahi*Blo + Alo*Bhi ----------
        float acc[8][4];
        #pragma unroll
        for (int j = 0; j < 8; j++)
            #pragma unroll
            for (int p = 0; p < 4; p++) acc[j][p] = 0.0f;

        #pragma unroll
        for (int s = 0; s < 8; s++) {
            uint32_t ah[4], al[4];
            ldsm_x4(ah, aHiBase + s*32);
            ldsm_x4(al, aLoBase + s*32);
            #pragma unroll
            for (int jp = 0; jp < 4; jp++) {
                uint32_t bh[4], bl[4];
                ldsm_x4_t(bh, bHiBase + s*(16*TSTRIDE) + jp*32);
                ldsm_x4_t(bl, bLoBase + s*(16*TSTRIDE) + jp*32);
                mma_bf16(acc[2*jp],     ah, bh[0], bh[1]);
                mma_bf16(acc[2*jp],     ah, bl[0], bl[1]);
                mma_bf16(acc[2*jp],     al, bh[0], bh[1]);
                mma_bf16(acc[2*jp + 1], ah, bh[2], bh[3]);
                mma_bf16(acc[2*jp + 1], ah, bl[2], bl[3]);
                mma_bf16(acc[2*jp + 1], al, bh[2], bh[3]);
            }
        }

        // ---------- heads directly from fragments ----------
        // Thread rows: r0 = 16*(wid>>1) + lane/4 and r0+8.
        // Thread cols: 64*(wid&1) + j*8 + (lane&3)*2 + {0,1}, j = 0..7.
        {
            float hd0 = 0.0f, hd1 = 0.0f;
            float c00 = 0.0f, c01 = 0.0f, c02 = 0.0f;
            float c10 = 0.0f, c11 = 0.0f, c12 = 0.0f;
            const int cbase = (wid & 1) * 64 + (lane & 3) * 2;
            #pragma unroll
            for (int j = 0; j < 8; j++) {
                int c = cbase + j*8;
                float2 b2v = *(const float2*)(sB2 + c);
                float2 wdv = *(const float2*)(sWD + c);
                float h00 = fmaxf(acc[j][0] + b2v.x, 0.0f);
                float h01 = fmaxf(acc[j][1] + b2v.y, 0.0f);
                float h80 = fmaxf(acc[j][2] + b2v.x, 0.0f);
                float h81 = fmaxf(acc[j][3] + b2v.y, 0.0f);
                hd0 = fmaf(h00, wdv.x, fmaf(h01, wdv.y, hd0));
                hd1 = fmaf(h80, wdv.x, fmaf(h81, wdv.y, hd1));
                float w0x = sWC[3*c+0], w0y = sWC[3*c+1], w0z = sWC[3*c+2];
                float w1x = sWC[3*c+3], w1y = sWC[3*c+4], w1z = sWC[3*c+5];
                c00 = fmaf(h00, w0x, fmaf(h01, w1x, c00));
                c01 = fmaf(h00, w0y, fmaf(h01, w1y, c01));
                c02 = fmaf(h00, w0z, fmaf(h01, w1z, c02));
                c10 = fmaf(h80, w0x, fmaf(h81, w1x, c10));
                c11 = fmaf(h80, w0y, fmaf(h81, w1y, c11));
                c12 = fmaf(h80, w0z, fmaf(h81, w1z, c12));
            }
            // quad reduce over (lane&3)
            #pragma unroll
            for (int o = 1; o <= 2; o <<= 1) {
                hd0 += __shfl_xor_sync(0xffffffffu, hd0, o);
                hd1 += __shfl_xor_sync(0xffffffffu, hd1, o);
                c00 += __shfl_xor_sync(0xffffffffu, c00, o);
                c01 += __shfl_xor_sync(0xffffffffu, c01, o);
                c02 += __shfl_xor_sync(0xffffffffu, c02, o);
                c10 += __shfl_xor_sync(0xffffffffu, c10, o);
                c11 += __shfl_xor_sync(0xffffffffu, c11, o);
                c12 += __shfl_xor_sync(0xffffffffu, c12, o);
            }
            if ((lane & 3) == 0) {
                float* dst = (wid & 1) ? sHB : sHA;
                int t0 = (wid >> 1)*16 + (lane >> 2);
                dst[t0*4 + 0] = hd0;
                dst[t0*4 + 1] = c00;
                dst[t0*4 + 2] = c01;
                dst[t0*4 + 3] = c02;
                dst[(t0+8)*4 + 0] = hd1;
                dst[(t0+8)*4 + 1] = c10;
                dst[(t0+8)*4 + 2] = c11;
                dst[(t0+8)*4 + 3] = c12;
            }
        }
        __syncthreads();

        // ---------- per-sample activations + sd (threads < 128) ----------
        float my_sd = 0.0f, mc0 = 0.0f, mc1 = 0.0f, mc2 = 0.0f;
        if (tid < TSAMP) {
            float accd = sHA[tid*4 + 0] + sHB[tid*4 + 0];
            float ac0  = sHA[tid*4 + 1] + sHB[tid*4 + 1];
            float ac1  = sHA[tid*4 + 2] + sHB[tid*4 + 2];
            float ac2  = sHA[tid*4 + 3] + sHB[tid*4 + 3];
            // SH conditioning (rows 128..143 of Wc)
            float inv_n = 1.0f / dnorm;
            float Ysh[16];
            sh3(dx*inv_n, dy*inv_n, dz*inv_n, Ysh);
            #pragma unroll
            for (int q = 0; q < SHDIM; q++) {
                float wq = Ysh[q];
                ac0 = fmaf(wq, sWC[(HID + q)*3 + 0], ac0);
                ac1 = fmaf(wq, sWC[(HID + q)*3 + 1], ac1);
                ac2 = fmaf(wq, sWC[(HID + q)*3 + 2], ac2);
            }
            float zz = accd + sBC[3];
            float sig = fmaxf(zz, 0.0f) + log1pf(expf(-fabsf(zz)));
            float m = sMSK[tid];
            sig *= m;
            mc0 = m / (1.0f + expf(-(ac0 + sBC[0])));
            mc1 = m / (1.0f + expf(-(ac1 + sBC[1])));
            mc2 = m / (1.0f + expf(-(ac2 + sBC[2])));
            float tsv  = sTS[tid];
            float tnxt = (tid < TSAMP - 1) ? sTS[tid + 1] : (tfar_c * RAYEXT);
            my_sd = sig * (tnxt - tsv) * dnorm;
        }

        // ---------- inclusive scan of sd over samples (warps 0-3 carry data) ----------
        float v = my_sd;
        #pragma unroll
        for (int o = 1; o < 32; o <<= 1) {
            float n = __shfl_up_sync(0xffffffffu, v, o);
            if (lane >= o) v += n;
        }
        if (wid < 4 && lane == 31) sWS[wid] = v;
        __syncthreads();
        float woff = 0.0f;
        if (wid < 4) {
            #pragma unroll
            for (int q = 0; q < 4; q++) woff += (q < wid) ? sWS[q] : 0.0f;
        }
        float csum = v + woff;

        float wgt = 0.0f;
        if (tid < TSAMP) wgt = expf(my_sd - csum) - expf(-csum);
        float rc0 = wgt * mc0, rc1 = wgt * mc1, rc2 = wgt * mc2;

        // ---------- block reduction ----------
        #pragma unroll
        for (int o = 16; o; o >>= 1) {
            rc0 += __shfl_xor_sync(0xffffffffu, rc0, o);
            rc1 += __shfl_xor_sync(0xffffffffu, rc1, o);
            rc2 += __shfl_xor_sync(0xffffffffu, rc2, o);
            wgt += __shfl_xor_sync(0xffffffffu, wgt, o);
        }
        if (wid < 4 && lane == 0) {
            sRED[wid*4 + 0] = rc0;
            sRED[wid*4 + 1] = rc1;
            sRED[wid*4 + 2] = rc2;
            sRED[wid*4 + 3] = wgt;
        }
        __syncthreads();
        if (tid == 0) {
            float o0 = 0.0f, o1 = 0.0f, o2 = 0.0f, o3 = 0.0f;
            #pragma unroll
            for (int q = 0; q < 4; q++) {
                o0 += sRED[q*4 + 0];
                o1 += sRED[q*4 + 1];
                o2 += sRED[q*4 + 2];
                o3 += sRED[q*4 + 3];
            }
            float4 res;
            res.x = active ? o0 : 0.0f;
            res.y = active ? o1 : 0.0f;
            res.z = active ? o2 : 0.0f;
            res.w = active ? o3 : 0.0f;
            *(float4*)(out + (size_t)r*4) = res;
        }
        __syncthreads();   // protect sTS/sX/... against next iteration's writes
    }
}

extern "C" void kernel_launch(void* const* d_in, const int* in_sizes, int n_in,
                              void* d_out, int out_size) {
    const float* origins = (const float*)d_in[0];
    const float* dirs    = (const float*)d_in[1];
    const float* u       = (const float*)d_in[2];
    const float* W1      = (const float*)d_in[3];
    const float* b1      = (const float*)d_in[4];
    const float* W2      = (const float*)d_in[5];
    const float* b2      = (const float*)d_in[6];
    const float* Wd      = (const float*)d_in[7];
    const float* bd      = (const float*)d_in[8];
    const float* Wc      = (const float*)d_in[9];
    const float* bc      = (const float*)d_in[10];
    float* out = (float*)d_out;

    int dev = 0, nsm = 148;
    cudaGetDevice(&dev);
    cudaDeviceGetAttribute(&nsm, cudaDevAttrMultiProcessorCount, dev);

    cudaFuncSetAttribute(radiance_kernel,
                         cudaFuncAttributeMaxDynamicSharedMemorySize, SMEM_BYTES);
    radiance_kernel<<<nsm, NTHREADS, SMEM_BYTES>>>(
        origins, dirs, u, W1, b1, W2, b2, Wd, bd, Wc, bc, out);
}

// round 5
// speedup vs baseline: 3.1634x; 1.1292x over previous
#include <cuda_runtime.h>
#include <cuda_bf16.h>
#include <cstdint>
#include <math.h>

// Problem constants
#define NRAYS   8192
#define TSAMP   128
#define HID     128
#define SHDIM   16
#define RAYEXT  10.0f
#define NTHREADS 512

// ---------------- warp-level tensor-core helpers ----------------
__device__ __forceinline__ void ldsm_x4(uint32_t* r, uint32_t addr) {
    asm volatile("ldmatrix.sync.aligned.m8n8.x4.shared.b16 {%0,%1,%2,%3}, [%4];"
        : "=r"(r[0]), "=r"(r[1]), "=r"(r[2]), "=r"(r[3]) : "r"(addr));
}
__device__ __forceinline__ void ldsm_x4_t(uint32_t* r, uint32_t addr) {
    asm volatile("ldmatrix.sync.aligned.m8n8.x4.trans.shared.b16 {%0,%1,%2,%3}, [%4];"
        : "=r"(r[0]), "=r"(r[1]), "=r"(r[2]), "=r"(r[3]) : "r"(addr));
}
__device__ __forceinline__ void mma_bf16(float* d, const uint32_t* a,
                                         uint32_t b0, uint32_t b1) {
    asm volatile("mma.sync.aligned.m16n8k16.row.col.f32.bf16.bf16.f32 "
        "{%0,%1,%2,%3}, {%4,%5,%6,%7}, {%8,%9}, {%0,%1,%2,%3};"
        : "+f"(d[0]), "+f"(d[1]), "+f"(d[2]), "+f"(d[3])
        : "r"(a[0]), "r"(a[1]), "r"(a[2]), "r"(a[3]), "r"(b0), "r"(b1));
}
__device__ __forceinline__ uint32_t smem_u32(const void* p) {
    uint32_t a;
    asm("{ .reg .u64 t; cvta.to.shared.u64 t, %1; cvt.u32.u64 %0, t; }"
        : "=r"(a) : "l"(p));
    return a;
}
__device__ __forceinline__ uint32_t pack_bf2(__nv_bfloat16 a, __nv_bfloat16 b) {
    __nv_bfloat162 t = __halves2bfloat162(a, b);
    return *reinterpret_cast<uint32_t*>(&t);
}

// ---------------- SMEM layout ----------------
// bf16 tiles, row stride 136 elements = 272 bytes (16B-aligned, conflict-free LDSM)
#define TSTRIDE  272
#define A_TILE   69632          // 256 * 272
#define B_TILE   34816          // 128 * 272
#define OFF_AHI  0
#define OFF_ALO  69632
#define OFF_BHI  139264
#define OFF_BLO  174080
#define OFF_F    208896
// float-region offsets (in floats)
#define F_W1   0       // 384
#define F_B1   384     // 128
#define F_B2   512     // 128
#define F_WD   640     // 128
#define F_WC   768     // 432
#define F_BC   1200    // 4 (bc0,bc1,bc2,bd)
#define F_TS   1216    // 256
#define F_X    1472    // 256
#define F_Y    1728    // 256
#define F_Z    1984    // 256
#define F_MSK  2240    // 256
#define F_WS   2496    // 16
#define F_RED  2512    // 64
#define F_HD   2576    // 256*4
#define F_TOTAL 3600
#define SMEM_BYTES (OFF_F + F_TOTAL * 4)

__device__ __forceinline__ void sh3(float x, float y, float z, float* Y) {
    float x2 = x*x, y2 = y*y, z2 = z*z;
    float xy = x*y, yz = y*z, xz = x*z;
    Y[0]  = 0.282094791773878f;
    Y[1]  = -0.48860251190292f * y;
    Y[2]  = 0.48860251190292f * z;
    Y[3]  = -0.48860251190292f * x;
    Y[4]  = 1.0925484305920792f * xy;
    Y[5]  = -1.0925484305920792f * yz;
    Y[6]  = 0.94617469575756f * z2 - 0.31539156525252f;
    Y[7]  = -1.0925484305920792f * xz;
    Y[8]  = 0.5462742152960396f * (x2 - y2);
    Y[9]  = 0.5900435899266435f * y * (-3.0f * x2 + y2);
    Y[10] = 2.8906114426405538f * xy * z;
    Y[11] = 0.4570457994644658f * y * (1.0f - 5.0f * z2);
    Y[12] = 0.3731763325901154f * z * (5.0f * z2 - 3.0f);
    Y[13] = 0.4570457994644658f * x * (1.0f - 5.0f * z2);
    Y[14] = 1.445305721320277f * z * (x2 - y2);
    Y[15] = 0.5900435899266435f * x * (-x2 + 3.0f * y2);
}

__device__ __forceinline__ void split_bf16(float v, __nv_bfloat16& hi, __nv_bfloat16& lo) {
    hi = __float2bfloat16(v);
    lo = __float2bfloat16(v - __bfloat162float(hi));
}

__global__ __launch_bounds__(NTHREADS, 1)
void radiance_kernel(const float* __restrict__ origins,
                     const float* __restrict__ dirs,
                     const float* __restrict__ u,
                     const float* __restrict__ W1,
                     const float* __restrict__ b1,
                     const float* __restrict__ W2,
                     const float* __restrict__ b2,
                     const float* __restrict__ Wd,
                     const float* __restrict__ bd,
                     const float* __restrict__ Wc,
                     const float* __restrict__ bc,
                     float* __restrict__ out)
{
    extern __shared__ char smc[];
    float* sf   = (float*)(smc + OFF_F);
    float* sW1  = sf + F_W1;
    float* sB1  = sf + F_B1;
    float* sB2  = sf + F_B2;
    float* sWD  = sf + F_WD;
    float* sWC  = sf + F_WC;
    float* sBC  = sf + F_BC;
    float* sTS  = sf + F_TS;
    float* sX   = sf + F_X;
    float* sY   = sf + F_Y;
    float* sZ   = sf + F_Z;
    float* sMSK = sf + F_MSK;
    float* sWS  = sf + F_WS;
    float* sRED = sf + F_RED;
    float* sHD  = sf + F_HD;

    const uint32_t sbase = smem_u32(smc);
    const int tid  = threadIdx.x;
    const int wid  = tid >> 5;
    const int lane = tid & 31;

    // ================= one-time staging (persistent CTA) =================
    for (int i = tid; i < 384; i += NTHREADS) sW1[i] = W1[i];
    if (tid < 128) {
        sB1[tid] = b1[tid];
        sB2[tid] = b2[tid];
        sWD[tid] = Wd[tid];
    }
    for (int i = tid; i < 432; i += NTHREADS) sWC[i] = Wc[i];
    if (tid < 3) sBC[tid] = bc[tid];
    if (tid == 3) sBC[3] = bd[0];

    // W2 -> Bhi/Blo [k][n] bf16 (native layout, coalesced)
    {
        #pragma unroll
        for (int g = 0; g < 8; g++) {
            int idx4 = g * NTHREADS + tid;     // 0..4095 (float4 index)
            int k    = idx4 >> 5;              // 0..127
            int n4   = (idx4 & 31) << 2;       // 0..124
            float4 v = __ldg((const float4*)W2 + idx4);
            __nv_bfloat16 h0, h1, h2, h3, l0, l1, l2, l3;
            split_bf16(v.x, h0, l0);
            split_bf16(v.y, h1, l1);
            split_bf16(v.z, h2, l2);
            split_bf16(v.w, h3, l3);
            uint32_t off = (uint32_t)(k * TSTRIDE + n4 * 2);
            *(uint2*)(smc + OFF_BHI + off) = make_uint2(pack_bf2(h0, h1), pack_bf2(h2, h3));
            *(uint2*)(smc + OFF_BLO + off) = make_uint2(pack_bf2(l0, l1), pack_bf2(l2, l3));
        }
    }
    __syncthreads();

    // GEMM addressing (fixed per thread):
    // Warp w owns A rows [16w, 16w+16); cols in two passes of 64.
    const uint32_t aHiBase = sbase + OFF_AHI
        + (uint32_t)((wid*16 + (lane & 15)) * TSTRIDE + (lane >> 4) * 16);
    const uint32_t aLoBase = aHiBase + A_TILE;
    const int gg = lane >> 3, ii = lane & 7;
    const uint32_t bRow = (uint32_t)(((gg & 1)*8 + ii) * TSTRIDE + (gg >> 1) * 16);
    const uint32_t bHiBase = sbase + OFF_BHI + bRow;
    const uint32_t bLoBase = bHiBase + B_TILE;

    // ================= persistent loop: 2 rays per iteration =================
    for (int r0 = blockIdx.x * 2; r0 < NRAYS; r0 += gridDim.x * 2) {

        // ---------- ray setup: thread handles ray (tid>>7)&1 ----------
        const int ridx = (tid >> 7) & 1;
        const int r = r0 + ridx;
        const float ox = __ldg(origins + 3*r + 0);
        const float oy = __ldg(origins + 3*r + 1);
        const float oz = __ldg(origins + 3*r + 2);
        const float dx = __ldg(dirs + 3*r + 0);
        const float dy = __ldg(dirs + 3*r + 1);
        const float dz = __ldg(dirs + 3*r + 2);

        float i0 = 1.0f/dx, i1 = 1.0f/dy, i2 = 1.0f/dz;
        float a0 = (-1.0f - ox)*i0, b0 = (1.0f - ox)*i0;
        float a1 = (-1.0f - oy)*i1, b1_ = (1.0f - oy)*i1;
        float a2 = (-1.0f - oz)*i2, b2_ = (1.0f - oz)*i2;
        float mn0 = fminf(a0,b0), mx0 = fmaxf(a0,b0);
        float mn1 = fminf(a1,b1_), mx1 = fmaxf(a1,b1_);
        float mn2 = fminf(a2,b2_), mx2 = fmaxf(a2,b2_);
        float tnear = fmaxf(fmaxf(fmaxf(mn0, mn1), mn2), 0.0f);
        float tfar  = fminf(fminf(mx0, mx1), mx2);
        bool  active = (tfar > tnear);
        float tfar_c = fmaxf(tfar, tnear + 1e-3f);
        float dnorm = sqrtf(dx*dx + dy*dy + dz*dz);

        // ---------- sample positions: threads < 256, sample tid (row = tid) ----------
        if (tid < 2*TSAMP) {
            int t = tid & 127;
            float uu = __ldg(u + r*TSAMP + t);
            float frac = ((float)t + uu) * (1.0f/(float)TSAMP);
            float ts = tnear + (tfar_c - tnear) * frac;
            float px = ox + dx*ts, py = oy + dy*ts, pz = oz + dz*ts;
            bool inb = (fabsf(px) <= 1.0f) && (fabsf(py) <= 1.0f) && (fabsf(pz) <= 1.0f);
            sTS[tid] = ts;
            sX[tid] = px; sY[tid] = py; sZ[tid] = pz;
            sMSK[tid] = (inb && active) ? 1.0f : 0.0f;
        }
        __syncthreads();

        // ---------- layer1: A = relu(X@W1+b1) -> bf16 hi/lo [row][k], 256 rows ----------
        {
            int t  = tid & 255;
            int j0 = (tid >> 8) * 64;
            float px = sX[t], py = sY[t], pz = sZ[t];
            #pragma unroll
            for (int g = 0; g < 8; g++) {
                uint32_t hp[4], lp[4];
                #pragma unroll
                for (int i = 0; i < 8; i += 2) {
                    int j = j0 + g*8 + i;
                    float v0 = fmaf(px, sW1[j],
                               fmaf(py, sW1[128 + j],
                               fmaf(pz, sW1[256 + j], sB1[j])));
                    float v1 = fmaf(px, sW1[j + 1],
                               fmaf(py, sW1[128 + j + 1],
                               fmaf(pz, sW1[256 + j + 1], sB1[j + 1])));
                    v0 = fmaxf(v0, 0.0f);
                    v1 = fmaxf(v1, 0.0f);
                    __nv_bfloat16 h0, h1, l0, l1;
                    split_bf16(v0, h0, l0);
                    split_bf16(v1, h1, l1);
                    hp[i >> 1] = pack_bf2(h0, h1);
                    lp[i >> 1] = pack_bf2(l0, l1);
                }
                uint32_t off = (uint32_t)(t * TSTRIDE + (j0 + g*8) * 2);
                *(uint4*)(smc + OFF_AHI + off) = make_uint4(hp[0], hp[1], hp[2], hp[3]);
                *(uint4*)(smc + OFF_ALO + off) = make_uint4(lp[0], lp[1], lp[2], lp[3]);
            }
        }
        __syncthreads();

        // ---------- GEMM + fused heads: two 64-col passes, acc reused ----------
        float hd0 = 0.0f, hd1 = 0.0f;
        float c00 = 0.0f, c01 = 0.0f, c02 = 0.0f;
        float c10 = 0.0f, c11 = 0.0f, c12 = 0.0f;

        #pragma unroll
        for (int pass = 0; pass < 2; pass++) {
            float acc[8][4];
            #pragma unroll
            for (int j = 0; j < 8; j++)
                #pragma unroll
                for (int p = 0; p < 4; p++) acc[j][p] = 0.0f;

            const uint32_t bH = bHiBase + (uint32_t)(pass * 128);
            const uint32_t bL = bLoBase + (uint32_t)(pass * 128);

            #pragma unroll
            for (int s = 0; s < 8; s++) {
                uint32_t ah[4], al[4];
                ldsm_x4(ah, aHiBase + s*32);
                ldsm_x4(al, aLoBase + s*32);
                #pragma unroll
                for (int jp = 0; jp < 4; jp++) {
                    uint32_t bh[4], bl[4];
                    ldsm_x4_t(bh, bH + s*(16*TSTRIDE) + jp*32);
                    ldsm_x4_t(bl, bL + s*(16*TSTRIDE) + jp*32);
                    mma_bf16(acc[2*jp],     ah, bh[0], bh[1]);
                    mma_bf16(acc[2*jp],     ah, bl[0], bl[1]);
                    mma_bf16(acc[2*jp],     al, bh[0], bh[1]);
                    mma_bf16(acc[2*jp + 1], ah, bh[2], bh[3]);
                    mma_bf16(acc[2*jp + 1], ah, bl[2], bl[3]);
                    mma_bf16(acc[2*jp + 1], al, bh[2], bh[3]);
                }
            }

            // fold this pass's 64 cols into head partials
            const int cbase = pass * 64 + (lane & 3) * 2;
            #pragma unroll
            for (int j = 0; j < 8; j++) {
                int c = cbase + j*8;
                float2 b2v = *(const float2*)(sB2 + c);
                float2 wdv = *(const float2*)(sWD + c);
                float h00 = fmaxf(acc[j][0] + b2v.x, 0.0f);
                float h01 = fmaxf(acc[j][1] + b2v.y, 0.0f);
                float h80 = fmaxf(acc[j][2] + b2v.x, 0.0f);
                float h81 = fmaxf(acc[j][3] + b2v.y, 0.0f);
                hd0 = fmaf(h00, wdv.x, fmaf(h01, wdv.y, hd0));
                hd1 = fmaf(h80, wdv.x, fmaf(h81, wdv.y, hd1));
                float w0x = sWC[3*c+0], w0y = sWC[3*c+1], w0z = sWC[3*c+2];
                float w1x = sWC[3*c+3], w1y = sWC[3*c+4], w1z = sWC[3*c+5];
                c00 = fmaf(h00, w0x, fmaf(h01, w1x, c00));
                c01 = fmaf(h00, w0y, fmaf(h01, w1y, c01));
                c02 = fmaf(h00, w0z, fmaf(h01, w1z, c02));
                c10 = fmaf(h80, w0x, fmaf(h81, w1x, c10));
                c11 = fmaf(h80, w0y, fmaf(h81, w1y, c11));
                c12 = fmaf(h80, w0z, fmaf(h81, w1z, c12));
            }
        }

        // quad reduce over (lane&3), then store per-row head vector
        #pragma unroll
        for (int o = 1; o <= 2; o <<= 1) {
            hd0 += __shfl_xor_sync(0xffffffffu, hd0, o);
            hd1 += __shfl_xor_sync(0xffffffffu, hd1, o);
            c00 += __shfl_xor_sync(0xffffffffu, c00, o);
            c01 += __shfl_xor_sync(0xffffffffu, c01, o);
            c02 += __shfl_xor_sync(0xffffffffu, c02, o);
            c10 += __shfl_xor_sync(0xffffffffu, c10, o);
            c11 += __shfl_xor_sync(0xffffffffu, c11, o);
            c12 += __shfl_xor_sync(0xffffffffu, c12, o);
        }
        if ((lane & 3) == 0) {
            int row = wid*16 + (lane >> 2);
            sHD[row*4 + 0] = hd0;
            sHD[row*4 + 1] = c00;
            sHD[row*4 + 2] = c01;
            sHD[row*4 + 3] = c02;
            sHD[(row+8)*4 + 0] = hd1;
            sHD[(row+8)*4 + 1] = c10;
            sHD[(row+8)*4 + 2] = c11;
            sHD[(row+8)*4 + 3] = c12;
        }
        __syncthreads();

        // ---------- per-sample activations + sd (threads < 256) ----------
        float my_sd = 0.0f, mc0 = 0.0f, mc1 = 0.0f, mc2 = 0.0f;
        if (tid < 2*TSAMP) {
            float accd = sHD[tid*4 + 0];
            float ac0  = sHD[tid*4 + 1];
            float ac1  = sHD[tid*4 + 2];
            float ac2  = sHD[tid*4 + 3];
            // SH conditioning (rows 128..143 of Wc)
            float inv_n = 1.0f / dnorm;
            float Ysh[16];
            sh3(dx*inv_n, dy*inv_n, dz*inv_n, Ysh);
            #pragma unroll
            for (int q = 0; q < SHDIM; q++) {
                float wq = Ysh[q];
                ac0 = fmaf(wq, sWC[(HID + q)*3 + 0], ac0);
                ac1 = fmaf(wq, sWC[(HID + q)*3 + 1], ac1);
                ac2 = fmaf(wq, sWC[(HID + q)*3 + 2], ac2);
            }
            float zz = accd + sBC[3];
            float sig = fmaxf(zz, 0.0f) + log1pf(expf(-fabsf(zz)));
            float m = sMSK[tid];
            sig *= m;
            mc0 = m / (1.0f + expf(-(ac0 + sBC[0])));
            mc1 = m / (1.0f + expf(-(ac1 + sBC[1])));
            mc2 = m / (1.0f + expf(-(ac2 + sBC[2])));
            float tsv  = sTS[tid];
            float tnxt = ((tid & 127) < TSAMP - 1) ? sTS[tid + 1] : (tfar_c * RAYEXT);
            my_sd = sig * (tnxt - tsv) * dnorm;
        }

        // ---------- two independent inclusive scans (warps 0-3 ray0, 4-7 ray1) ----------
        float v = my_sd;
        #pragma unroll
        for (int o = 1; o < 32; o <<= 1) {
            float n = __shfl_up_sync(0xffffffffu, v, o);
            if (lane >= o) v += n;
        }
        if (wid < 8 && lane == 31) sWS[wid] = v;
        __syncthreads();
        float woff = 0.0f;
        if (wid < 8) {
            int qb = wid & ~3;
            #pragma unroll
            for (int d = 0; d < 4; d++) {
                int q = qb + d;
                woff += (q < wid) ? sWS[q] : 0.0f;
            }
        }
        float csum = v + woff;

        float wgt = 0.0f;
        if (tid < 2*TSAMP) wgt = expf(my_sd - csum) - expf(-csum);
        float rc0 = wgt * mc0, rc1 = wgt * mc1, rc2 = wgt * mc2;

        // ---------- per-warp reduction ----------
        #pragma unroll
        for (int o = 16; o; o >>= 1) {
            rc0 += __shfl_xor_sync(0xffffffffu, rc0, o);
            rc1 += __shfl_xor_sync(0xffffffffu, rc1, o);
            rc2 += __shfl_xor_sync(0xffffffffu, rc2, o);
            wgt += __shfl_xor_sync(0xffffffffu, wgt, o);
        }
        if (wid < 8 && lane == 0) {
            sRED[wid*4 + 0] = rc0;
            sRED[wid*4 + 1] = rc1;
            sRED[wid*4 + 2] = rc2;
            sRED[wid*4 + 3] = wgt;
        }
        __syncthreads();
        // thread 0 writes ray0, thread 128 writes ray1 (each has its own 'active')
        if (tid == 0 || tid == 128) {
            int qb = ridx * 4;
            float o0 = 0.0f, o1 = 0.0f, o2 = 0.0f, o3 = 0.0f;
            #pragma unroll
            for (int d = 0; d < 4; d++) {
                o0 += sRED[(qb+d)*4 + 0];
                o1 += sRED[(qb+d)*4 + 1];
                o2 += sRED[(qb+d)*4 + 2];
                o3 += sRED[(qb+d)*4 + 3];
            }
            float4 res;
            res.x = active ? o0 : 0.0f;
            res.y = active ? o1 : 0.0f;
            res.z = active ? o2 : 0.0f;
            res.w = active ? o3 : 0.0f;
            *(float4*)(out + (size_t)r*4) = res;
        }
        __syncthreads();   // protect shared scratch against next iteration
    }
}

extern "C" void kernel_launch(void* const* d_in, const int* in_sizes, int n_in,
                              void* d_out, int out_size) {
    const float* origins = (const float*)d_in[0];
    const float* dirs    = (const float*)d_in[1];
    const float* u       = (const float*)d_in[2];
    const float* W1      = (const float*)d_in[3];
    const float* b1      = (const float*)d_in[4];
    const float* W2      = (const float*)d_in[5];
    const float* b2      = (const float*)d_in[6];
    const float* Wd      = (const float*)d_in[7];
    const float* bd      = (const float*)d_in[8];
    const float* Wc      = (const float*)d_in[9];
    const float* bc      = (const float*)d_in[10];
    float* out = (float*)d_out;

    int dev = 0, nsm = 148;
    cudaGetDevice(&dev);
    cudaDeviceGetAttribute(&nsm, cudaDevAttrMultiProcessorCount, dev);

    cudaFuncSetAttribute(radiance_kernel,
                         cudaFuncAttributeMaxDynamicSharedMemorySize, SMEM_BYTES);
    radiance_kernel<<<nsm, NTHREADS, SMEM_BYTES>>>(
        origins, dirs, u, W1, b1, W2, b2, Wd, bd, Wc, bc, out);
}

// round 6
// speedup vs baseline: 3.2485x; 1.0269x over previous
#include <cuda_runtime.h>
#include <cuda_bf16.h>
#include <cstdint>
#include <math.h>

// Problem constants
#define NRAYS   8192
#define TSAMP   128
#define HID     128
#define SHDIM   16
#define RAYEXT  10.0f
#define NTHREADS 512

// ---------------- warp-level tensor-core helpers ----------------
__device__ __forceinline__ void ldsm_x4(uint32_t* r, uint32_t addr) {
    asm volatile("ldmatrix.sync.aligned.m8n8.x4.shared.b16 {%0,%1,%2,%3}, [%4];"
        : "=r"(r[0]), "=r"(r[1]), "=r"(r[2]), "=r"(r[3]) : "r"(addr));
}
__device__ __forceinline__ void ldsm_x4_t(uint32_t* r, uint32_t addr) {
    asm volatile("ldmatrix.sync.aligned.m8n8.x4.trans.shared.b16 {%0,%1,%2,%3}, [%4];"
        : "=r"(r[0]), "=r"(r[1]), "=r"(r[2]), "=r"(r[3]) : "r"(addr));
}
__device__ __forceinline__ void mma_bf16(float* d, const uint32_t* a,
                                         uint32_t b0, uint32_t b1) {
    asm volatile("mma.sync.aligned.m16n8k16.row.col.f32.bf16.bf16.f32 "
        "{%0,%1,%2,%3}, {%4,%5,%6,%7}, {%8,%9}, {%0,%1,%2,%3};"
        : "+f"(d[0]), "+f"(d[1]), "+f"(d[2]), "+f"(d[3])
        : "r"(a[0]), "r"(a[1]), "r"(a[2]), "r"(a[3]), "r"(b0), "r"(b1));
}
__device__ __forceinline__ uint32_t smem_u32(const void* p) {
    uint32_t a;
    asm("{ .reg .u64 t; cvta.to.shared.u64 t, %1; cvt.u32.u64 %0, t; }"
        : "=r"(a) : "l"(p));
    return a;
}
__device__ __forceinline__ uint32_t pack_bf2(__nv_bfloat16 a, __nv_bfloat16 b) {
    __nv_bfloat162 t = __halves2bfloat162(a, b);
    return *reinterpret_cast<uint32_t*>(&t);
}

// ---------------- SMEM layout ----------------
#define TSTRIDE  272
#define A_TILE   69632          // 256 * 272
#define B_TILE   34816          // 128 * 272
#define OFF_AHI  0
#define OFF_ALO  69632
#define OFF_BHI  139264
#define OFF_BLO  174080
#define OFF_F    208896
// float-region offsets (in floats)
#define F_W1   0       // 384
#define F_B1   384     // 128
#define F_B2   512     // 128
#define F_WD   640     // 128
#define F_WC   768     // 432
#define F_BC   1200    // 4 (bc0,bc1,bc2,bd)
#define F_TS   1216    // 256
#define F_MSK  1472    // 256
#define F_WS   1728    // 16
#define F_RED  1744    // 64
#define F_RAY  1808    // 16 (2 rays x 8: tfar_c,dnorm,active,dx,dy,dz)
#define F_HD   1824    // 256*4
#define F_TOTAL 2848
#define SMEM_BYTES (OFF_F + F_TOTAL * 4)

__device__ __forceinline__ void sh3(float x, float y, float z, float* Y) {
    float x2 = x*x, y2 = y*y, z2 = z*z;
    float xy = x*y, yz = y*z, xz = x*z;
    Y[0]  = 0.282094791773878f;
    Y[1]  = -0.48860251190292f * y;
    Y[2]  = 0.48860251190292f * z;
    Y[3]  = -0.48860251190292f * x;
    Y[4]  = 1.0925484305920792f * xy;
    Y[5]  = -1.0925484305920792f * yz;
    Y[6]  = 0.94617469575756f * z2 - 0.31539156525252f;
    Y[7]  = -1.0925484305920792f * xz;
    Y[8]  = 0.5462742152960396f * (x2 - y2);
    Y[9]  = 0.5900435899266435f * y * (-3.0f * x2 + y2);
    Y[10] = 2.8906114426405538f * xy * z;
    Y[11] = 0.4570457994644658f * y * (1.0f - 5.0f * z2);
    Y[12] = 0.3731763325901154f * z * (5.0f * z2 - 3.0f);
    Y[13] = 0.4570457994644658f * x * (1.0f - 5.0f * z2);
    Y[14] = 1.445305721320277f * z * (x2 - y2);
    Y[15] = 0.5900435899266435f * x * (-x2 + 3.0f * y2);
}

__device__ __forceinline__ void split_bf16(float v, __nv_bfloat16& hi, __nv_bfloat16& lo) {
    hi = __float2bfloat16(v);
    lo = __float2bfloat16(v - __bfloat162float(hi));
}

__global__ __launch_bounds__(NTHREADS, 1)
void radiance_kernel(const float* __restrict__ origins,
                     const float* __restrict__ dirs,
                     const float* __restrict__ u,
                     const float* __restrict__ W1,
                     const float* __restrict__ b1,
                     const float* __restrict__ W2,
                     const float* __restrict__ b2,
                     const float* __restrict__ Wd,
                     const float* __restrict__ bd,
                     const float* __restrict__ Wc,
                     const float* __restrict__ bc,
                     float* __restrict__ out)
{
    extern __shared__ char smc[];
    float* sf   = (float*)(smc + OFF_F);
    float* sW1  = sf + F_W1;
    float* sB1  = sf + F_B1;
    float* sB2  = sf + F_B2;
    float* sWD  = sf + F_WD;
    float* sWC  = sf + F_WC;
    float* sBC  = sf + F_BC;
    float* sTS  = sf + F_TS;
    float* sMSK = sf + F_MSK;
    float* sWS  = sf + F_WS;
    float* sRED = sf + F_RED;
    float* sRAY = sf + F_RAY;
    float* sHD  = sf + F_HD;

    const uint32_t sbase = smem_u32(smc);
    const int tid  = threadIdx.x;
    const int wid  = tid >> 5;
    const int lane = tid & 31;

    // ================= one-time staging (persistent CTA) =================
    for (int i = tid; i < 384; i += NTHREADS) sW1[i] = W1[i];
    if (tid < 128) {
        sB1[tid] = b1[tid];
        sB2[tid] = b2[tid];
        sWD[tid] = Wd[tid];
    }
    for (int i = tid; i < 432; i += NTHREADS) sWC[i] = Wc[i];
    if (tid < 3) sBC[tid] = bc[tid];
    if (tid == 3) sBC[3] = bd[0];

    // W2 -> Bhi/Blo [k][n] bf16 (native layout, coalesced)
    {
        #pragma unroll
        for (int g = 0; g < 8; g++) {
            int idx4 = g * NTHREADS + tid;     // 0..4095 (float4 index)
            int k    = idx4 >> 5;              // 0..127
            int n4   = (idx4 & 31) << 2;       // 0..124
            float4 v = __ldg((const float4*)W2 + idx4);
            __nv_bfloat16 h0, h1, h2, h3, l0, l1, l2, l3;
            split_bf16(v.x, h0, l0);
            split_bf16(v.y, h1, l1);
            split_bf16(v.z, h2, l2);
            split_bf16(v.w, h3, l3);
            uint32_t off = (uint32_t)(k * TSTRIDE + n4 * 2);
            *(uint2*)(smc + OFF_BHI + off) = make_uint2(pack_bf2(h0, h1), pack_bf2(h2, h3));
            *(uint2*)(smc + OFF_BLO + off) = make_uint2(pack_bf2(l0, l1), pack_bf2(l2, l3));
        }
    }
    __syncthreads();

    // GEMM addressing (fixed per thread):
    // Warp w owns A rows [16w, 16w+16) exclusively.
    const uint32_t aHiBase = sbase + OFF_AHI
        + (uint32_t)((wid*16 + (lane & 15)) * TSTRIDE + (lane >> 4) * 16);
    const uint32_t aLoBase = aHiBase + A_TILE;
    const int gg = lane >> 3, ii = lane & 7;
    const uint32_t bRow = (uint32_t)(((gg & 1)*8 + ii) * TSTRIDE + (gg >> 1) * 16);
    const uint32_t bHiBase = sbase + OFF_BHI + bRow;
    const uint32_t bLoBase = bHiBase + B_TILE;

    // Per-warp constants for the barrier-free front-end
    const int wridx = wid >> 3;             // warp's ray (0/1)
    const int rloc  = (wid & 7) * 16 + (lane & 15);   // sample idx 0..127
    const int arow  = wid * 16 + (lane & 15);         // A-tile row 0..255

    // ================= persistent loop: 2 rays per iteration =================
    for (int r0 = blockIdx.x * 2; r0 < NRAYS; r0 += gridDim.x * 2) {

        // ======== BARRIER-FREE PER-WARP FRONT-END ========
        const int wr = r0 + wridx;
        const float ox = __ldg(origins + 3*wr + 0);
        const float oy = __ldg(origins + 3*wr + 1);
        const float oz = __ldg(origins + 3*wr + 2);
        const float dx = __ldg(dirs + 3*wr + 0);
        const float dy = __ldg(dirs + 3*wr + 1);
        const float dz = __ldg(dirs + 3*wr + 2);

        float i0 = 1.0f/dx, i1 = 1.0f/dy, i2 = 1.0f/dz;
        float a0 = (-1.0f - ox)*i0, b0 = (1.0f - ox)*i0;
        float a1 = (-1.0f - oy)*i1, b1_ = (1.0f - oy)*i1;
        float a2 = (-1.0f - oz)*i2, b2_ = (1.0f - oz)*i2;
        float mn0 = fminf(a0,b0), mx0 = fmaxf(a0,b0);
        float mn1 = fminf(a1,b1_), mx1 = fmaxf(a1,b1_);
        float mn2 = fminf(a2,b2_), mx2 = fmaxf(a2,b2_);
        float tnear = fmaxf(fmaxf(fmaxf(mn0, mn1), mn2), 0.0f);
        float tfar  = fminf(fminf(mx0, mx1), mx2);
        float activef = (tfar > tnear) ? 1.0f : 0.0f;
        float tfar_c = fmaxf(tfar, tnear + 1e-3f);
        float dnorm = sqrtf(dx*dx + dy*dy + dz*dz);

        if ((wid & 7) == 0 && lane == 0) {
            float* rs = sRAY + wridx*8;
            rs[0] = tfar_c; rs[1] = dnorm; rs[2] = activef;
            rs[3] = dx; rs[4] = dy; rs[5] = dz;
        }

        // sample position for this lane's row (lanes 16-31 duplicate 0-15; benign)
        float uu = __ldg(u + wr*TSAMP + rloc);
        float frac = ((float)rloc + uu) * (1.0f/(float)TSAMP);
        float ts = tnear + (tfar_c - tnear) * frac;
        float px = ox + dx*ts, py = oy + dy*ts, pz = oz + dz*ts;
        bool inb = (fabsf(px) <= 1.0f) && (fabsf(py) <= 1.0f) && (fabsf(pz) <= 1.0f);
        sTS[wridx*TSAMP + rloc] = ts;
        sMSK[wridx*TSAMP + rloc] = (inb && activef != 0.0f) ? 1.0f : 0.0f;

        // layer1 for own row, own k-half: j0..j0+63
        {
            const int j0 = (lane >> 4) * 64;
            #pragma unroll
            for (int g = 0; g < 8; g++) {
                uint32_t hp[4], lp[4];
                #pragma unroll
                for (int i = 0; i < 8; i += 2) {
                    int j = j0 + g*8 + i;
                    float v0 = fmaf(px, sW1[j],
                               fmaf(py, sW1[128 + j],
                               fmaf(pz, sW1[256 + j], sB1[j])));
                    float v1 = fmaf(px, sW1[j + 1],
                               fmaf(py, sW1[128 + j + 1],
                               fmaf(pz, sW1[256 + j + 1], sB1[j + 1])));
                    v0 = fmaxf(v0, 0.0f);
                    v1 = fmaxf(v1, 0.0f);
                    __nv_bfloat16 h0, h1, l0, l1;
                    split_bf16(v0, h0, l0);
                    split_bf16(v1, h1, l1);
                    hp[i >> 1] = pack_bf2(h0, h1);
                    lp[i >> 1] = pack_bf2(l0, l1);
                }
                uint32_t off = (uint32_t)(arow * TSTRIDE + (j0 + g*8) * 2);
                *(uint4*)(smc + OFF_AHI + off) = make_uint4(hp[0], hp[1], hp[2], hp[3]);
                *(uint4*)(smc + OFF_ALO + off) = make_uint4(lp[0], lp[1], lp[2], lp[3]);
            }
        }
        __syncwarp();   // own rows written by own warp only

        // ---------- GEMM + fused heads: two 64-col passes ----------
        float hd0 = 0.0f, hd1 = 0.0f;
        float c00 = 0.0f, c01 = 0.0f, c02 = 0.0f;
        float c10 = 0.0f, c11 = 0.0f, c12 = 0.0f;

        #pragma unroll
        for (int pass = 0; pass < 2; pass++) {
            float acc[8][4];
            #pragma unroll
            for (int j = 0; j < 8; j++)
                #pragma unroll
                for (int p = 0; p < 4; p++) acc[j][p] = 0.0f;

            const uint32_t bH = bHiBase + (uint32_t)(pass * 128);
            const uint32_t bL = bLoBase + (uint32_t)(pass * 128);

            #pragma unroll
            for (int s = 0; s < 8; s++) {
                uint32_t ah[4], al[4];
                ldsm_x4(ah, aHiBase + s*32);
                ldsm_x4(al, aLoBase + s*32);
                #pragma unroll
                for (int jp = 0; jp < 4; jp++) {
                    uint32_t bh[4], bl[4];
                    ldsm_x4_t(bh, bH + s*(16*TSTRIDE) + jp*32);
                    ldsm_x4_t(bl, bL + s*(16*TSTRIDE) + jp*32);
                    mma_bf16(acc[2*jp],     ah, bh[0], bh[1]);
                    mma_bf16(acc[2*jp],     ah, bl[0], bl[1]);
                    mma_bf16(acc[2*jp],     al, bh[0], bh[1]);
                    mma_bf16(acc[2*jp + 1], ah, bh[2], bh[3]);
                    mma_bf16(acc[2*jp + 1], ah, bl[2], bl[3]);
                    mma_bf16(acc[2*jp + 1], al, bh[2], bh[3]);
                }
            }

            // fold this pass's 64 cols into head partials
            const int cbase = pass * 64 + (lane & 3) * 2;
            #pragma unroll
            for (int j = 0; j < 8; j++) {
                int c = cbase + j*8;
                float2 b2v = *(const float2*)(sB2 + c);
                float2 wdv = *(const float2*)(sWD + c);
                float h00 = fmaxf(acc[j][0] + b2v.x, 0.0f);
                float h01 = fmaxf(acc[j][1] + b2v.y, 0.0f);
                float h80 = fmaxf(acc[j][2] + b2v.x, 0.0f);
                float h81 = fmaxf(acc[j][3] + b2v.y, 0.0f);
                hd0 = fmaf(h00, wdv.x, fmaf(h01, wdv.y, hd0));
                hd1 = fmaf(h80, wdv.x, fmaf(h81, wdv.y, hd1));
                float w0x = sWC[3*c+0], w0y = sWC[3*c+1], w0z = sWC[3*c+2];
                float w1x = sWC[3*c+3], w1y = sWC[3*c+4], w1z = sWC[3*c+5];
                c00 = fmaf(h00, w0x, fmaf(h01, w1x, c00));
                c01 = fmaf(h00, w0y, fmaf(h01, w1y, c01));
                c02 = fmaf(h00, w0z, fmaf(h01, w1z, c02));
                c10 = fmaf(h80, w0x, fmaf(h81, w1x, c10));
                c11 = fmaf(h80, w0y, fmaf(h81, w1y, c11));
                c12 = fmaf(h80, w0z, fmaf(h81, w1z, c12));
            }
        }

        // quad reduce over (lane&3), store per-row head vector
        #pragma unroll
        for (int o = 1; o <= 2; o <<= 1) {
            hd0 += __shfl_xor_sync(0xffffffffu, hd0, o);
            hd1 += __shfl_xor_sync(0xffffffffu, hd1, o);
            c00 += __shfl_xor_sync(0xffffffffu, c00, o);
            c01 += __shfl_xor_sync(0xffffffffu, c01, o);
            c02 += __shfl_xor_sync(0xffffffffu, c02, o);
            c10 += __shfl_xor_sync(0xffffffffu, c10, o);
            c11 += __shfl_xor_sync(0xffffffffu, c11, o);
            c12 += __shfl_xor_sync(0xffffffffu, c12, o);
        }
        if ((lane & 3) == 0) {
            int row = wid*16 + (lane >> 2);
            sHD[row*4 + 0] = hd0;
            sHD[row*4 + 1] = c00;
            sHD[row*4 + 2] = c01;
            sHD[row*4 + 3] = c02;
            sHD[(row+8)*4 + 0] = hd1;
            sHD[(row+8)*4 + 1] = c10;
            sHD[(row+8)*4 + 2] = c11;
            sHD[(row+8)*4 + 3] = c12;
        }
        __syncthreads();   // barrier 1: sHD/sTS/sMSK/sRAY ready block-wide

        // ======== EPILOGUE (threads < 256; tid = global sample row) ========
        float my_sd = 0.0f, mc0 = 0.0f, mc1 = 0.0f, mc2 = 0.0f;
        float e_tfar_c = 0.0f, e_active = 0.0f;
        if (tid < 2*TSAMP) {
            const float* rs = sRAY + ((tid >> 7) & 1) * 8;
            e_tfar_c = rs[0];
            float e_dnorm = rs[1];
            e_active = rs[2];
            float edx = rs[3], edy = rs[4], edz = rs[5];

            float accd = sHD[tid*4 + 0];
            float ac0  = sHD[tid*4 + 1];
            float ac1  = sHD[tid*4 + 2];
            float ac2  = sHD[tid*4 + 3];
            float inv_n = 1.0f / e_dnorm;
            float Ysh[16];
            sh3(edx*inv_n, edy*inv_n, edz*inv_n, Ysh);
            #pragma unroll
            for (int q = 0; q < SHDIM; q++) {
                float wq = Ysh[q];
                ac0 = fmaf(wq, sWC[(HID + q)*3 + 0], ac0);
                ac1 = fmaf(wq, sWC[(HID + q)*3 + 1], ac1);
                ac2 = fmaf(wq, sWC[(HID + q)*3 + 2], ac2);
            }
            float zz = accd + sBC[3];
            float sig = fmaxf(zz, 0.0f) + log1pf(expf(-fabsf(zz)));
            float m = sMSK[tid];
            sig *= m;
            mc0 = m / (1.0f + expf(-(ac0 + sBC[0])));
            mc1 = m / (1.0f + expf(-(ac1 + sBC[1])));
            mc2 = m / (1.0f + expf(-(ac2 + sBC[2])));
            float tsv  = sTS[tid];
            float tnxt = ((tid & 127) < TSAMP - 1) ? sTS[tid + 1] : (e_tfar_c * RAYEXT);
            my_sd = sig * (tnxt - tsv) * e_dnorm;
        }

        // two independent inclusive scans (warps 0-3 ray0, 4-7 ray1)
        float v = my_sd;
        #pragma unroll
        for (int o = 1; o < 32; o <<= 1) {
            float n = __shfl_up_sync(0xffffffffu, v, o);
            if (lane >= o) v += n;
        }
        if (wid < 8 && lane == 31) sWS[wid] = v;
        __syncthreads();
        float woff = 0.0f;
        if (wid < 8) {
            int qb = wid & ~3;
            #pragma unroll
            for (int d = 0; d < 4; d++) {
                int q = qb + d;
                woff += (q < wid) ? sWS[q] : 0.0f;
            }
        }
        float csum = v + woff;

        float wgt = 0.0f;
        if (tid < 2*TSAMP) wgt = expf(my_sd - csum) - expf(-csum);
        float rc0 = wgt * mc0, rc1 = wgt * mc1, rc2 = wgt * mc2;

        #pragma unroll
        for (int o = 16; o; o >>= 1) {
            rc0 += __shfl_xor_sync(0xffffffffu, rc0, o);
            rc1 += __shfl_xor_sync(0xffffffffu, rc1, o);
            rc2 += __shfl_xor_sync(0xffffffffu, rc2, o);
            wgt += __shfl_xor_sync(0xffffffffu, wgt, o);
        }
        if (wid < 8 && lane == 0) {
            sRED[wid*4 + 0] = rc0;
            sRED[wid*4 + 1] = rc1;
            sRED[wid*4 + 2] = rc2;
            sRED[wid*4 + 3] = wgt;
        }
        __syncthreads();
        if (tid == 0 || tid == 128) {
            int er = (tid >> 7) & 1;
            int qb = er * 4;
            float o0 = 0.0f, o1 = 0.0f, o2 = 0.0f, o3 = 0.0f;
            #pragma unroll
            for (int d = 0; d < 4; d++) {
                o0 += sRED[(qb+d)*4 + 0];
                o1 += sRED[(qb+d)*4 + 1];
                o2 += sRED[(qb+d)*4 + 2];
                o3 += sRED[(qb+d)*4 + 3];
            }
            bool act = (sRAY[er*8 + 2] != 0.0f);
            float4 res;
            res.x = act ? o0 : 0.0f;
            res.y = act ? o1 : 0.0f;
            res.z = act ? o2 : 0.0f;
            res.w = act ? o3 : 0.0f;
            *(float4*)(out + (size_t)(r0 + er)*4) = res;
        }
        __syncthreads();   // protect shared scratch before next iteration
    }
}

extern "C" void kernel_launch(void* const* d_in, const int* in_sizes, int n_in,
                              void* d_out, int out_size) {
    const float* origins = (const float*)d_in[0];
    const float* dirs    = (const float*)d_in[1];
    const float* u       = (const float*)d_in[2];
    const float* W1      = (const float*)d_in[3];
    const float* b1      = (const float*)d_in[4];
    const float* W2      = (const float*)d_in[5];
    const float* b2      = (const float*)d_in[6];
    const float* Wd      = (const float*)d_in[7];
    const float* bd      = (const float*)d_in[8];
    const float* Wc      = (const float*)d_in[9];
    const float* bc      = (const float*)d_in[10];
    float* out = (float*)d_out;

    int dev = 0, nsm = 148;
    cudaGetDevice(&dev);
    cudaDeviceGetAttribute(&nsm, cudaDevAttrMultiProcessorCount, dev);

    cudaFuncSetAttribute(radiance_kernel,
                         cudaFuncAttributeMaxDynamicSharedMemorySize, SMEM_BYTES);
    radiance_kernel<<<nsm, NTHREADS, SMEM_BYTES>>>(
        origins, dirs, u, W1, b1, W2, b2, Wd, bd, Wc, bc, out);
}

// round 7
// speedup vs baseline: 4.0649x; 1.2513x over previous
#include <cuda_runtime.h>
#include <cuda_fp16.h>
#include <cstdint>
#include <math.h>

// Problem constants
#define NRAYS   8192
#define TSAMP   128
#define HID     128
#define SHDIM   16
#define RAYEXT  10.0f
#define NTHREADS 512

// ---------------- warp-level tensor-core helpers ----------------
__device__ __forceinline__ void ldsm_x4(uint32_t* r, uint32_t addr) {
    asm volatile("ldmatrix.sync.aligned.m8n8.x4.shared.b16 {%0,%1,%2,%3}, [%4];"
        : "=r"(r[0]), "=r"(r[1]), "=r"(r[2]), "=r"(r[3]) : "r"(addr));
}
__device__ __forceinline__ void ldsm_x4_t(uint32_t* r, uint32_t addr) {
    asm volatile("ldmatrix.sync.aligned.m8n8.x4.trans.shared.b16 {%0,%1,%2,%3}, [%4];"
        : "=r"(r[0]), "=r"(r[1]), "=r"(r[2]), "=r"(r[3]) : "r"(addr));
}
__device__ __forceinline__ void mma_f16(float* d, const uint32_t* a,
                                        uint32_t b0, uint32_t b1) {
    asm volatile("mma.sync.aligned.m16n8k16.row.col.f32.f16.f16.f32 "
        "{%0,%1,%2,%3}, {%4,%5,%6,%7}, {%8,%9}, {%0,%1,%2,%3};"
        : "+f"(d[0]), "+f"(d[1]), "+f"(d[2]), "+f"(d[3])
        : "r"(a[0]), "r"(a[1]), "r"(a[2]), "r"(a[3]), "r"(b0), "r"(b1));
}
__device__ __forceinline__ uint32_t smem_u32(const void* p) {
    uint32_t a;
    asm("{ .reg .u64 t; cvta.to.shared.u64 t, %1; cvt.u32.u64 %0, t; }"
        : "=r"(a) : "l"(p));
    return a;
}
__device__ __forceinline__ uint32_t pack_h2(__half a, __half b) {
    __half2 t = __halves2half2(a, b);
    return *reinterpret_cast<uint32_t*>(&t);
}
__device__ __forceinline__ void split_f16(float v, __half& hi, __half& lo) {
    hi = __float2half(v);
    lo = __float2half(v - __half2float(hi));
}

// ---------------- SMEM layout ----------------
#define TSTRIDE  272
#define A_TILE   69632          // 256 * 272
#define OFF_AHI  0
#define OFF_ALO  69632
#define OFF_BHI  139264         // single fp16 B tile (128 * 272)
#define OFF_F    174080
// float-region offsets (in floats)
#define F_W1   0       // 384
#define F_B1   384     // 128
#define F_B2   512     // 128
#define F_WD   640     // 128
#define F_WC   768     // 432
#define F_BC   1200    // 4 (bc0,bc1,bc2,bd)
#define F_TS   1216    // 256
#define F_MSK  1472    // 256
#define F_WS   1728    // 16
#define F_RED  1744    // 64
#define F_RAY  1808    // 16 (2 rays x 8: tfar_c,dnorm,active,dx,dy,dz)
#define F_HD   1824    // 256*4
#define F_TOTAL 2848
#define SMEM_BYTES (OFF_F + F_TOTAL * 4)

__device__ __forceinline__ void sh3(float x, float y, float z, float* Y) {
    float x2 = x*x, y2 = y*y, z2 = z*z;
    float xy = x*y, yz = y*z, xz = x*z;
    Y[0]  = 0.282094791773878f;
    Y[1]  = -0.48860251190292f * y;
    Y[2]  = 0.48860251190292f * z;
    Y[3]  = -0.48860251190292f * x;
    Y[4]  = 1.0925484305920792f * xy;
    Y[5]  = -1.0925484305920792f * yz;
    Y[6]  = 0.94617469575756f * z2 - 0.31539156525252f;
    Y[7]  = -1.0925484305920792f * xz;
    Y[8]  = 0.5462742152960396f * (x2 - y2);
    Y[9]  = 0.5900435899266435f * y * (-3.0f * x2 + y2);
    Y[10] = 2.8906114426405538f * xy * z;
    Y[11] = 0.4570457994644658f * y * (1.0f - 5.0f * z2);
    Y[12] = 0.3731763325901154f * z * (5.0f * z2 - 3.0f);
    Y[13] = 0.4570457994644658f * x * (1.0f - 5.0f * z2);
    Y[14] = 1.445305721320277f * z * (x2 - y2);
    Y[15] = 0.5900435899266435f * x * (-x2 + 3.0f * y2);
}

__global__ __launch_bounds__(NTHREADS, 1)
void radiance_kernel(const float* __restrict__ origins,
                     const float* __restrict__ dirs,
                     const float* __restrict__ u,
                     const float* __restrict__ W1,
                     const float* __restrict__ b1,
                     const float* __restrict__ W2,
                     const float* __restrict__ b2,
                     const float* __restrict__ Wd,
                     const float* __restrict__ bd,
                     const float* __restrict__ Wc,
                     const float* __restrict__ bc,
                     float* __restrict__ out)
{
    extern __shared__ char smc[];
    float* sf   = (float*)(smc + OFF_F);
    float* sW1  = sf + F_W1;
    float* sB1  = sf + F_B1;
    float* sB2  = sf + F_B2;
    float* sWD  = sf + F_WD;
    float* sWC  = sf + F_WC;
    float* sBC  = sf + F_BC;
    float* sTS  = sf + F_TS;
    float* sMSK = sf + F_MSK;
    float* sWS  = sf + F_WS;
    float* sRED = sf + F_RED;
    float* sRAY = sf + F_RAY;
    float* sHD  = sf + F_HD;

    const uint32_t sbase = smem_u32(smc);
    const int tid  = threadIdx.x;
    const int wid  = tid >> 5;
    const int lane = tid & 31;

    // ================= one-time staging (persistent CTA) =================
    for (int i = tid; i < 384; i += NTHREADS) sW1[i] = W1[i];
    if (tid < 128) {
        sB1[tid] = b1[tid];
        sB2[tid] = b2[tid];
        sWD[tid] = Wd[tid];
    }
    for (int i = tid; i < 432; i += NTHREADS) sWC[i] = Wc[i];
    if (tid < 3) sBC[tid] = bc[tid];
    if (tid == 3) sBC[3] = bd[0];

    // W2 -> B fp16 [k][n] (native layout, coalesced; one static rounding)
    {
        #pragma unroll
        for (int g = 0; g < 8; g++) {
            int idx4 = g * NTHREADS + tid;     // 0..4095 (float4 index)
            int k    = idx4 >> 5;              // 0..127
            int n4   = (idx4 & 31) << 2;       // 0..124
            float4 v = __ldg((const float4*)W2 + idx4);
            uint32_t p0 = pack_h2(__float2half(v.x), __float2half(v.y));
            uint32_t p1 = pack_h2(__float2half(v.z), __float2half(v.w));
            uint32_t off = (uint32_t)(k * TSTRIDE + n4 * 2);
            *(uint2*)(smc + OFF_BHI + off) = make_uint2(p0, p1);
        }
    }
    __syncthreads();

    // GEMM addressing (fixed per thread):
    // Warp w owns A rows [16w, 16w+16) exclusively.
    const uint32_t aHiBase = sbase + OFF_AHI
        + (uint32_t)((wid*16 + (lane & 15)) * TSTRIDE + (lane >> 4) * 16);
    const uint32_t aLoBase = aHiBase + A_TILE;
    const int gg = lane >> 3, ii = lane & 7;
    const uint32_t bRow = (uint32_t)(((gg & 1)*8 + ii) * TSTRIDE + (gg >> 1) * 16);
    const uint32_t bHiBase = sbase + OFF_BHI + bRow;

    // Per-warp constants for the barrier-free front-end
    const int wridx = wid >> 3;                       // warp's ray (0/1)
    const int rloc  = (wid & 7) * 16 + (lane & 15);   // sample idx 0..127
    const int arow  = wid * 16 + (lane & 15);         // A-tile row 0..255

    // ================= persistent loop: 2 rays per iteration =================
    for (int r0 = blockIdx.x * 2; r0 < NRAYS; r0 += gridDim.x * 2) {

        // ======== BARRIER-FREE PER-WARP FRONT-END ========
        const int wr = r0 + wridx;
        const float ox = __ldg(origins + 3*wr + 0);
        const float oy = __ldg(origins + 3*wr + 1);
        const float oz = __ldg(origins + 3*wr + 2);
        const float dx = __ldg(dirs + 3*wr + 0);
        const float dy = __ldg(dirs + 3*wr + 1);
        const float dz = __ldg(dirs + 3*wr + 2);

        float i0 = 1.0f/dx, i1 = 1.0f/dy, i2 = 1.0f/dz;
        float a0 = (-1.0f - ox)*i0, b0 = (1.0f - ox)*i0;
        float a1 = (-1.0f - oy)*i1, b1_ = (1.0f - oy)*i1;
        float a2 = (-1.0f - oz)*i2, b2_ = (1.0f - oz)*i2;
        float mn0 = fminf(a0,b0), mx0 = fmaxf(a0,b0);
        float mn1 = fminf(a1,b1_), mx1 = fmaxf(a1,b1_);
        float mn2 = fminf(a2,b2_), mx2 = fmaxf(a2,b2_);
        float tnear = fmaxf(fmaxf(fmaxf(mn0, mn1), mn2), 0.0f);
        float tfar  = fminf(fminf(mx0, mx1), mx2);
        float activef = (tfar > tnear) ? 1.0f : 0.0f;
        float tfar_c = fmaxf(tfar, tnear + 1e-3f);
        float dnorm = sqrtf(dx*dx + dy*dy + dz*dz);

        if ((wid & 7) == 0 && lane == 0) {
            float* rs = sRAY + wridx*8;
            rs[0] = tfar_c; rs[1] = dnorm; rs[2] = activef;
            rs[3] = dx; rs[4] = dy; rs[5] = dz;
        }

        // sample position for this lane's row (lanes 16-31 duplicate 0-15; benign)
        float uu = __ldg(u + wr*TSAMP + rloc);
        float frac = ((float)rloc + uu) * (1.0f/(float)TSAMP);
        float ts = tnear + (tfar_c - tnear) * frac;
        float px = ox + dx*ts, py = oy + dy*ts, pz = oz + dz*ts;
        bool inb = (fabsf(px) <= 1.0f) && (fabsf(py) <= 1.0f) && (fabsf(pz) <= 1.0f);
        sTS[wridx*TSAMP + rloc] = ts;
        sMSK[wridx*TSAMP + rloc] = (inb && activef != 0.0f) ? 1.0f : 0.0f;

        // layer1 for own row, own k-half: A = relu(X@W1+b1) as fp16 hi/lo
        {
            const int j0 = (lane >> 4) * 64;
            #pragma unroll
            for (int g = 0; g < 8; g++) {
                uint32_t hp[4], lp[4];
                #pragma unroll
                for (int i = 0; i < 8; i += 2) {
                    int j = j0 + g*8 + i;
                    float v0 = fmaf(px, sW1[j],
                               fmaf(py, sW1[128 + j],
                               fmaf(pz, sW1[256 + j], sB1[j])));
                    float v1 = fmaf(px, sW1[j + 1],
                               fmaf(py, sW1[128 + j + 1],
                               fmaf(pz, sW1[256 + j + 1], sB1[j + 1])));
                    v0 = fmaxf(v0, 0.0f);
                    v1 = fmaxf(v1, 0.0f);
                    __half h0, h1, l0, l1;
                    split_f16(v0, h0, l0);
                    split_f16(v1, h1, l1);
                    hp[i >> 1] = pack_h2(h0, h1);
                    lp[i >> 1] = pack_h2(l0, l1);
                }
                uint32_t off = (uint32_t)(arow * TSTRIDE + (j0 + g*8) * 2);
                *(uint4*)(smc + OFF_AHI + off) = make_uint4(hp[0], hp[1], hp[2], hp[3]);
                *(uint4*)(smc + OFF_ALO + off) = make_uint4(lp[0], lp[1], lp[2], lp[3]);
            }
        }
        __syncwarp();   // own rows written by own warp only

        // ---------- GEMM + fused heads: two 64-col passes ----------
        float hd0 = 0.0f, hd1 = 0.0f;
        float c00 = 0.0f, c01 = 0.0f, c02 = 0.0f;
        float c10 = 0.0f, c11 = 0.0f, c12 = 0.0f;

        #pragma unroll
        for (int pass = 0; pass < 2; pass++) {
            float acc[8][4];
            #pragma unroll
            for (int j = 0; j < 8; j++)
                #pragma unroll
                for (int p = 0; p < 4; p++) acc[j][p] = 0.0f;

            const uint32_t bH = bHiBase + (uint32_t)(pass * 128);

            #pragma unroll
            for (int s = 0; s < 8; s++) {
                uint32_t ah[4], al[4];
                ldsm_x4(ah, aHiBase + s*32);
                ldsm_x4(al, aLoBase + s*32);
                #pragma unroll
                for (int jp = 0; jp < 4; jp++) {
                    uint32_t bh[4];
                    ldsm_x4_t(bh, bH + s*(16*TSTRIDE) + jp*32);
                    mma_f16(acc[2*jp],     ah, bh[0], bh[1]);
                    mma_f16(acc[2*jp],     al, bh[0], bh[1]);
                    mma_f16(acc[2*jp + 1], ah, bh[2], bh[3]);
                    mma_f16(acc[2*jp + 1], al, bh[2], bh[3]);
                }
            }

            // fold this pass's 64 cols into head partials
            const int cbase = pass * 64 + (lane & 3) * 2;
            #pragma unroll
            for (int j = 0; j < 8; j++) {
                int c = cbase + j*8;
                float2 b2v = *(const float2*)(sB2 + c);
                float2 wdv = *(const float2*)(sWD + c);
                float h00 = fmaxf(acc[j][0] + b2v.x, 0.0f);
                float h01 = fmaxf(acc[j][1] + b2v.y, 0.0f);
                float h80 = fmaxf(acc[j][2] + b2v.x, 0.0f);
                float h81 = fmaxf(acc[j][3] + b2v.y, 0.0f);
                hd0 = fmaf(h00, wdv.x, fmaf(h01, wdv.y, hd0));
                hd1 = fmaf(h80, wdv.x, fmaf(h81, wdv.y, hd1));
                float w0x = sWC[3*c+0], w0y = sWC[3*c+1], w0z = sWC[3*c+2];
                float w1x = sWC[3*c+3], w1y = sWC[3*c+4], w1z = sWC[3*c+5];
                c00 = fmaf(h00, w0x, fmaf(h01, w1x, c00));
                c01 = fmaf(h00, w0y, fmaf(h01, w1y, c01));
                c02 = fmaf(h00, w0z, fmaf(h01, w1z, c02));
                c10 = fmaf(h80, w0x, fmaf(h81, w1x, c10));
                c11 = fmaf(h80, w0y, fmaf(h81, w1y, c11));
                c12 = fmaf(h80, w0z, fmaf(h81, w1z, c12));
            }
        }

        // quad reduce over (lane&3), store per-row head vector
        #pragma unroll
        for (int o = 1; o <= 2; o <<= 1) {
            hd0 += __shfl_xor_sync(0xffffffffu, hd0, o);
            hd1 += __shfl_xor_sync(0xffffffffu, hd1, o);
            c00 += __shfl_xor_sync(0xffffffffu, c00, o);
            c01 += __shfl_xor_sync(0xffffffffu, c01, o);
            c02 += __shfl_xor_sync(0xffffffffu, c02, o);
            c10 += __shfl_xor_sync(0xffffffffu, c10, o);
            c11 += __shfl_xor_sync(0xffffffffu, c11, o);
            c12 += __shfl_xor_sync(0xffffffffu, c12, o);
        }
        if ((lane & 3) == 0) {
            int row = wid*16 + (lane >> 2);
            sHD[row*4 + 0] = hd0;
            sHD[row*4 + 1] = c00;
            sHD[row*4 + 2] = c01;
            sHD[row*4 + 3] = c02;
            sHD[(row+8)*4 + 0] = hd1;
            sHD[(row+8)*4 + 1] = c10;
            sHD[(row+8)*4 + 2] = c11;
            sHD[(row+8)*4 + 3] = c12;
        }
        __syncthreads();   // barrier 1: sHD/sTS/sMSK/sRAY ready block-wide

        // ======== EPILOGUE (threads < 256; tid = global sample row) ========
        float my_sd = 0.0f, mc0 = 0.0f, mc1 = 0.0f, mc2 = 0.0f;
        if (tid < 2*TSAMP) {
            const float* rs = sRAY + ((tid >> 7) & 1) * 8;
            float e_tfar_c = rs[0];
            float e_dnorm = rs[1];
            float edx = rs[3], edy = rs[4], edz = rs[5];

            float accd = sHD[tid*4 + 0];
            float ac0  = sHD[tid*4 + 1];
            float ac1  = sHD[tid*4 + 2];
            float ac2  = sHD[tid*4 + 3];
            float inv_n = 1.0f / e_dnorm;
            float Ysh[16];
            sh3(edx*inv_n, edy*inv_n, edz*inv_n, Ysh);
            #pragma unroll
            for (int q = 0; q < SHDIM; q++) {
                float wq = Ysh[q];
                ac0 = fmaf(wq, sWC[(HID + q)*3 + 0], ac0);
                ac1 = fmaf(wq, sWC[(HID + q)*3 + 1], ac1);
                ac2 = fmaf(wq, sWC[(HID + q)*3 + 2], ac2);
            }
            float zz = accd + sBC[3];
            float sig = fmaxf(zz, 0.0f) + log1pf(expf(-fabsf(zz)));
            float m = sMSK[tid];
            sig *= m;
            mc0 = m / (1.0f + expf(-(ac0 + sBC[0])));
            mc1 = m / (1.0f + expf(-(ac1 + sBC[1])));
            mc2 = m / (1.0f + expf(-(ac2 + sBC[2])));
            float tsv  = sTS[tid];
            float tnxt = ((tid & 127) < TSAMP - 1) ? sTS[tid + 1] : (e_tfar_c * RAYEXT);
            my_sd = sig * (tnxt - tsv) * e_dnorm;
        }

        // two independent inclusive scans (warps 0-3 ray0, 4-7 ray1)
        float v = my_sd;
        #pragma unroll
        for (int o = 1; o < 32; o <<= 1) {
            float n = __shfl_up_sync(0xffffffffu, v, o);
            if (lane >= o) v += n;
        }
        if (wid < 8 && lane == 31) sWS[wid] = v;
        __syncthreads();
        float woff = 0.0f;
        if (wid < 8) {
            int qb = wid & ~3;
            #pragma unroll
            for (int d = 0; d < 4; d++) {
                int q = qb + d;
                woff += (q < wid) ? sWS[q] : 0.0f;
            }
        }
        float csum = v + woff;

        float wgt = 0.0f;
        if (tid < 2*TSAMP) wgt = expf(my_sd - csum) - expf(-csum);
        float rc0 = wgt * mc0, rc1 = wgt * mc1, rc2 = wgt * mc2;

        #pragma unroll
        for (int o = 16; o; o >>= 1) {
            rc0 += __shfl_xor_sync(0xffffffffu, rc0, o);
            rc1 += __shfl_xor_sync(0xffffffffu, rc1, o);
            rc2 += __shfl_xor_sync(0xffffffffu, rc2, o);
            wgt += __shfl_xor_sync(0xffffffffu, wgt, o);
        }
        if (wid < 8 && lane == 0) {
            sRED[wid*4 + 0] = rc0;
            sRED[wid*4 + 1] = rc1;
            sRED[wid*4 + 2] = rc2;
            sRED[wid*4 + 3] = wgt;
        }
        __syncthreads();
        if (tid == 0 || tid == 128) {
            int er = (tid >> 7) & 1;
            int qb = er * 4;
            float o0 = 0.0f, o1 = 0.0f, o2 = 0.0f, o3 = 0.0f;
            #pragma unroll
            for (int d = 0; d < 4; d++) {
                o0 += sRED[(qb+d)*4 + 0];
                o1 += sRED[(qb+d)*4 + 1];
                o2 += sRED[(qb+d)*4 + 2];
                o3 += sRED[(qb+d)*4 + 3];
            }
            bool act = (sRAY[er*8 + 2] != 0.0f);
            float4 res;
            res.x = act ? o0 : 0.0f;
            res.y = act ? o1 : 0.0f;
            res.z = act ? o2 : 0.0f;
            res.w = act ? o3 : 0.0f;
            *(float4*)(out + (size_t)(r0 + er)*4) = res;
        }
        __syncthreads();   // protect shared scratch before next iteration
    }
}

extern "C" void kernel_launch(void* const* d_in, const int* in_sizes, int n_in,
                              void* d_out, int out_size) {
    const float* origins = (const float*)d_in[0];
    const float* dirs    = (const float*)d_in[1];
    const float* u       = (const float*)d_in[2];
    const float* W1      = (const float*)d_in[3];
    const float* b1      = (const float*)d_in[4];
    const float* W2      = (const float*)d_in[5];
    const float* b2      = (const float*)d_in[6];
    const float* Wd      = (const float*)d_in[7];
    const float* bd      = (const float*)d_in[8];
    const float* Wc      = (const float*)d_in[9];
    const float* bc      = (const float*)d_in[10];
    float* out = (float*)d_out;

    int dev = 0, nsm = 148;
    cudaGetDevice(&dev);
    cudaDeviceGetAttribute(&nsm, cudaDevAttrMultiProcessorCount, dev);

    cudaFuncSetAttribute(radiance_kernel,
                         cudaFuncAttributeMaxDynamicSharedMemorySize, SMEM_BYTES);
    radiance_kernel<<<nsm, NTHREADS, SMEM_BYTES>>>(
        origins, dirs, u, W1, b1, W2, b2, Wd, bd, Wc, bc, out);
}